// round 1
// baseline (speedup 1.0000x reference)
#include <cuda_runtime.h>
#include <math.h>

#define B_    1024
#define D_    1024
#define H_    16
#define DH_   64
#define S_    50
#define P_    49
#define OUT_  1000
#define NTOK  (B_*P_)   // 50176 non-cls tokens

// ---------------- scratch (device globals; no allocation allowed) ----------
__device__ float g_N[(size_t)NTOK*D_];      // LN1 output for tokens 1..49 per batch
__device__ float g_V[(size_t)NTOK*D_];      // V for tokens 1..49 per batch
__device__ float g_scores[(size_t)NTOK*H_]; // pre-softmax scores (q0 . k_s)*32
__device__ float g_tok0[(size_t)B_*D_];     // tok row 0 after attention residual (then Y)
__device__ float g_Z[(size_t)B_*D_];        // LN2 output
__device__ float g_logits[(size_t)B_*OUT_];
__device__ float g_tok0c[D_];               // cls + pe(0)   (batch-invariant)
__device__ float g_q0[D_];                  // query for position 0 (batch-invariant)
__device__ float g_v0[D_];                  // value for position 0 (batch-invariant)
__device__ float g_score0[H_];              // score of cls attending to itself

// ---------------- helpers ---------------------------------------------------
__device__ __forceinline__ float pos_emb(int pos, int d) {
    float fd    = (float)(d & ~1);                      // d (even) or d-1 (odd)
    float denom = powf(10000.0f, fd * (1.0f / 1024.0f));
    float ang   = (float)pos / denom;
    return (d & 1) ? cosf(ang) : sinf(ang);
}

__device__ __forceinline__ float block_reduce_sum(float v, float* red) {
    int t = threadIdx.x;
    #pragma unroll
    for (int o = 16; o > 0; o >>= 1) v += __shfl_down_sync(0xffffffffu, v, o);
    if ((t & 31) == 0) red[t >> 5] = v;
    __syncthreads();
    if (t == 0) {
        float s = 0.f;
        int nw = blockDim.x >> 5;
        for (int i = 0; i < nw; i++) s += red[i];
        red[0] = s;
    }
    __syncthreads();
    float r = red[0];
    __syncthreads();
    return r;
}

__device__ __forceinline__ float block_reduce_max(float v, float* red) {
    int t = threadIdx.x;
    #pragma unroll
    for (int o = 16; o > 0; o >>= 1) v = fmaxf(v, __shfl_down_sync(0xffffffffu, v, o));
    if ((t & 31) == 0) red[t >> 5] = v;
    __syncthreads();
    if (t == 0) {
        float m = red[0];
        int nw = blockDim.x >> 5;
        for (int i = 1; i < nw; i++) m = fmaxf(m, red[i]);
        red[0] = m;
    }
    __syncthreads();
    float r = red[0];
    __syncthreads();
    return r;
}

// ---------------- K0: batch-invariant cls-row constants --------------------
__global__ __launch_bounds__(256) void k0_const(
    const float* __restrict__ cls, const float* __restrict__ ln1w, const float* __restrict__ ln1b,
    const float* __restrict__ Wq, const float* __restrict__ bq,
    const float* __restrict__ Wk, const float* __restrict__ bk,
    const float* __restrict__ Wv, const float* __restrict__ bv)
{
    __shared__ float tok[D_];
    __shared__ float n[D_];
    __shared__ float red[32];
    __shared__ float sacc[H_];
    int t = threadIdx.x;

    for (int d = t; d < D_; d += 256) tok[d] = cls[d] + pos_emb(0, d);
    if (t < H_) sacc[t] = 0.f;
    __syncthreads();

    float s = 0.f;
    for (int d = t; d < D_; d += 256) s += tok[d];
    float mu = block_reduce_sum(s, red) * (1.0f / D_);
    float vs = 0.f;
    for (int d = t; d < D_; d += 256) { float dv = tok[d] - mu; vs += dv * dv; }
    float var  = block_reduce_sum(vs, red) * (1.0f / D_);
    float rstd = rsqrtf(var + 1e-5f);

    for (int d = t; d < D_; d += 256) {
        n[d] = (tok[d] - mu) * rstd * ln1w[d] + ln1b[d];
        g_tok0c[d] = tok[d];
    }
    __syncthreads();

    for (int o = t; o < D_; o += 256) {
        int h = o >> 6, e = o & 63;
        const float* wq = Wq + h * 4096 + e * 64;
        const float* wk = Wk + h * 4096 + e * 64;
        const float* wv = Wv + h * 4096 + e * 64;
        const float* nh = n + h * 64;
        float q = 0.f, k = 0.f, v = 0.f;
        #pragma unroll 8
        for (int d = 0; d < 64; d++) {
            float xv = nh[d];
            q += xv * wq[d]; k += xv * wk[d]; v += xv * wv[d];
        }
        q += bq[o]; k += bk[o]; v += bv[o];
        g_q0[o] = q; g_v0[o] = v;
        atomicAdd(&sacc[h], q * k);
    }
    __syncthreads();
    if (t < H_) g_score0[t] = 32.0f * sacc[t];
}

// ---------------- K1a: patchify + patch-embed + pos-emb + LN1 --------------
__global__ __launch_bounds__(256) void k1a_tok_ln(
    const float* __restrict__ x, const float* __restrict__ Wp,
    const float* __restrict__ ln1w, const float* __restrict__ ln1b)
{
    int p = blockIdx.x;           // 0..48
    int b = blockIdx.y;           // 0..1023
    __shared__ float patch[16];
    __shared__ float tok[D_];
    __shared__ float red[32];
    int t = threadIdx.x;

    if (t < 16) {
        int i = t >> 2, j = t & 3, r = p / 7, c = p % 7;
        patch[t] = x[(size_t)b * 784 + (r * 4 + i) * 28 + (c * 4 + j)];
    }
    __syncthreads();

    int pos = p + 1;
    for (int d = t; d < D_; d += 256) {
        const float* wp = Wp + d * 16;
        float a = 0.f;
        #pragma unroll
        for (int s = 0; s < 16; s++) a += patch[s] * wp[s];
        tok[d] = a + pos_emb(pos, d);
    }
    __syncthreads();

    float s = 0.f;
    for (int d = t; d < D_; d += 256) s += tok[d];
    float mu = block_reduce_sum(s, red) * (1.0f / D_);
    float vs = 0.f;
    for (int d = t; d < D_; d += 256) { float dv = tok[d] - mu; vs += dv * dv; }
    float var  = block_reduce_sum(vs, red) * (1.0f / D_);
    float rstd = rsqrtf(var + 1e-5f);

    float* np = g_N + (size_t)(b * P_ + p) * D_;
    for (int d = t; d < D_; d += 256)
        np[d] = (tok[d] - mu) * rstd * ln1w[d] + ln1b[d];
}

// ---------------- K1b: batched per-head K/V projection + q0.k scores -------
// Block = 64 tokens x 1 head. smem-tiled 64x64x64 x2 (K and V).
__global__ __launch_bounds__(256) void k1b_kv(
    const float* __restrict__ Wk, const float* __restrict__ bk,
    const float* __restrict__ Wv, const float* __restrict__ bv)
{
    int h    = blockIdx.y;
    int tok0 = blockIdx.x * 64;
    __shared__ float Ns [64][65];
    __shared__ float Wks[64][65];
    __shared__ float Wvs[64][65];
    __shared__ float sacc[64];
    int t = threadIdx.x;

    for (int idx = t; idx < 4096; idx += 256) {
        int e = idx >> 6, d = idx & 63;
        Wks[e][d] = Wk[(size_t)h * 4096 + idx];
        Wvs[e][d] = Wv[(size_t)h * 4096 + idx];
        Ns [e][d] = g_N[(size_t)(tok0 + e) * D_ + h * 64 + d];
    }
    if (t < 64) sacc[t] = 0.f;
    __syncthreads();

    int tr = (t & 15) * 4;   // token sub-tile
    int tc = (t >> 4) * 4;   // e sub-tile
    float aK[4][4] = {}, aV[4][4] = {};
    #pragma unroll 8
    for (int d = 0; d < 64; d++) {
        float a0 = Ns[tr + 0][d], a1 = Ns[tr + 1][d], a2 = Ns[tr + 2][d], a3 = Ns[tr + 3][d];
        float kk0 = Wks[tc + 0][d], kk1 = Wks[tc + 1][d], kk2 = Wks[tc + 2][d], kk3 = Wks[tc + 3][d];
        float vv0 = Wvs[tc + 0][d], vv1 = Wvs[tc + 1][d], vv2 = Wvs[tc + 2][d], vv3 = Wvs[tc + 3][d];
        aK[0][0] += a0 * kk0; aK[0][1] += a0 * kk1; aK[0][2] += a0 * kk2; aK[0][3] += a0 * kk3;
        aK[1][0] += a1 * kk0; aK[1][1] += a1 * kk1; aK[1][2] += a1 * kk2; aK[1][3] += a1 * kk3;
        aK[2][0] += a2 * kk0; aK[2][1] += a2 * kk1; aK[2][2] += a2 * kk2; aK[2][3] += a2 * kk3;
        aK[3][0] += a3 * kk0; aK[3][1] += a3 * kk1; aK[3][2] += a3 * kk2; aK[3][3] += a3 * kk3;
        aV[0][0] += a0 * vv0; aV[0][1] += a0 * vv1; aV[0][2] += a0 * vv2; aV[0][3] += a0 * vv3;
        aV[1][0] += a1 * vv0; aV[1][1] += a1 * vv1; aV[1][2] += a1 * vv2; aV[1][3] += a1 * vv3;
        aV[2][0] += a2 * vv0; aV[2][1] += a2 * vv1; aV[2][2] += a2 * vv2; aV[2][3] += a2 * vv3;
        aV[3][0] += a3 * vv0; aV[3][1] += a3 * vv1; aV[3][2] += a3 * vv2; aV[3][3] += a3 * vv3;
    }

    float qv[4], bkv[4], bvv[4];
    #pragma unroll
    for (int j = 0; j < 4; j++) {
        qv[j]  = g_q0[h * 64 + tc + j];
        bkv[j] = bk  [h * 64 + tc + j];
        bvv[j] = bv  [h * 64 + tc + j];
    }
    #pragma unroll
    for (int i = 0; i < 4; i++) {
        float sp = 0.f;
        size_t vbase = (size_t)(tok0 + tr + i) * D_ + h * 64 + tc;
        #pragma unroll
        for (int j = 0; j < 4; j++) {
            float kval = aK[i][j] + bkv[j];
            g_V[vbase + j] = aV[i][j] + bvv[j];
            sp += qv[j] * kval;
        }
        atomicAdd(&sacc[tr + i], sp);
    }
    __syncthreads();
    if (t < 64) g_scores[(size_t)(tok0 + t) * H_ + h] = 32.0f * sacc[t];
}

// ---------------- K2: softmax(50) + weighted V + residual + LN2 ------------
__global__ __launch_bounds__(256) void k2_attn_ln2(
    const float* __restrict__ ln2w, const float* __restrict__ ln2b)
{
    int b = blockIdx.x;
    __shared__ float w[H_][52];
    __shared__ float tok[D_];
    __shared__ float red[32];
    int t = threadIdx.x;

    if (t < H_) {
        float sc[S_];
        sc[0] = g_score0[t];
        for (int s = 1; s < S_; s++)
            sc[s] = g_scores[(size_t)(b * P_ + s - 1) * H_ + t];
        float m = sc[0];
        for (int s = 1; s < S_; s++) m = fmaxf(m, sc[s]);
        float sum = 0.f;
        for (int s = 0; s < S_; s++) { float e = expf(sc[s] - m); w[t][s] = e; sum += e; }
        float inv = 1.f / sum;
        for (int s = 0; s < S_; s++) w[t][s] *= inv;
    }
    __syncthreads();

    for (int d = t; d < D_; d += 256) {
        int h = d >> 6;
        float a = w[h][0] * g_v0[d];
        for (int s = 1; s < S_; s++)
            a += w[h][s] * g_V[(size_t)(b * P_ + s - 1) * D_ + d];
        float tn = g_tok0c[d] + a;
        tok[d] = tn;
        g_tok0[(size_t)b * D_ + d] = tn;
    }
    __syncthreads();

    float s = 0.f;
    for (int d = t; d < D_; d += 256) s += tok[d];
    float mu = block_reduce_sum(s, red) * (1.0f / D_);
    float vs = 0.f;
    for (int d = t; d < D_; d += 256) { float dv = tok[d] - mu; vs += dv * dv; }
    float var  = block_reduce_sum(vs, red) * (1.0f / D_);
    float rstd = rsqrtf(var + 1e-5f);
    for (int d = t; d < D_; d += 256)
        g_Z[(size_t)b * D_ + d] = (tok[d] - mu) * rstd * ln2w[d] + ln2b[d];
}

// ---------------- generic NT GEMM body (C = [add +] A*B^T + bias) ----------
__device__ __forceinline__ void gemm_nt_body(
    const float* __restrict__ A, const float* __restrict__ Bm,
    const float* __restrict__ addm, const float* __restrict__ bias,
    float* __restrict__ C, int M, int N, int K, int addFlag)
{
    __shared__ float As[16][68];
    __shared__ float Bs[16][68];
    int t  = threadIdx.x;
    int tx = t & 15, ty = t >> 4;
    int m0 = blockIdx.y * 64, n0 = blockIdx.x * 64;
    float acc[4][4] = {};

    for (int k0 = 0; k0 < K; k0 += 16) {
        for (int idx = t; idx < 1024; idx += 256) {
            int mm = idx >> 4, kk = idx & 15;
            As[kk][mm] = A[(size_t)(m0 + mm) * K + k0 + kk];
            Bs[kk][mm] = (n0 + mm < N) ? Bm[(size_t)(n0 + mm) * K + k0 + kk] : 0.f;
        }
        __syncthreads();
        #pragma unroll
        for (int kk = 0; kk < 16; kk++) {
            float a[4], bb[4];
            #pragma unroll
            for (int i = 0; i < 4; i++) a[i]  = As[kk][ty * 4 + i];
            #pragma unroll
            for (int j = 0; j < 4; j++) bb[j] = Bs[kk][tx * 4 + j];
            #pragma unroll
            for (int i = 0; i < 4; i++)
                #pragma unroll
                for (int j = 0; j < 4; j++)
                    acc[i][j] += a[i] * bb[j];
        }
        __syncthreads();
    }

    #pragma unroll
    for (int i = 0; i < 4; i++) {
        int m = m0 + ty * 4 + i;
        #pragma unroll
        for (int j = 0; j < 4; j++) {
            int n = n0 + tx * 4 + j;
            if (n < N) {
                float v = acc[i][j] + bias[n];
                if (addFlag) v += addm[(size_t)m * N + n];
                C[(size_t)m * N + n] = v;
            }
        }
    }
}

// K3: Y = tok0 + Z @ Wm^T + bm   (in-place into g_tok0)
__global__ __launch_bounds__(256) void gemm_k3(const float* __restrict__ Wm,
                                               const float* __restrict__ bm) {
    gemm_nt_body(g_Z, Wm, g_tok0, bm, g_tok0, B_, D_, D_, 1);
}

// K4: logits = Y @ Wh^T + bh
__global__ __launch_bounds__(256) void gemm_k4(const float* __restrict__ Wh,
                                               const float* __restrict__ bh) {
    gemm_nt_body(g_tok0, Wh, nullptr, bh, g_logits, B_, OUT_, D_, 0);
}

// ---------------- K5: row softmax over 1000 logits --------------------------
__global__ __launch_bounds__(256) void k5_softmax(float* __restrict__ out) {
    int b = blockIdx.x;
    __shared__ float red[32];
    int t = threadIdx.x;
    const float* lg = g_logits + (size_t)b * OUT_;

    float m = -1e30f;
    for (int o = t; o < OUT_; o += 256) m = fmaxf(m, lg[o]);
    m = block_reduce_max(m, red);

    float s = 0.f;
    for (int o = t; o < OUT_; o += 256) s += expf(lg[o] - m);
    float sum = block_reduce_sum(s, red);
    float inv = 1.f / sum;

    float* ob = out + (size_t)b * OUT_;
    for (int o = t; o < OUT_; o += 256) ob[o] = expf(lg[o] - m) * inv;
}

// ---------------- launch -----------------------------------------------------
extern "C" void kernel_launch(void* const* d_in, const int* in_sizes, int n_in,
                              void* d_out, int out_size) {
    const float* x    = (const float*)d_in[0];
    const float* cls  = (const float*)d_in[1];
    const float* Wp   = (const float*)d_in[2];
    const float* ln1w = (const float*)d_in[3];
    const float* ln1b = (const float*)d_in[4];
    const float* Wq   = (const float*)d_in[5];
    const float* bq   = (const float*)d_in[6];
    const float* Wk   = (const float*)d_in[7];
    const float* bk   = (const float*)d_in[8];
    const float* Wv   = (const float*)d_in[9];
    const float* bv   = (const float*)d_in[10];
    const float* ln2w = (const float*)d_in[11];
    const float* ln2b = (const float*)d_in[12];
    const float* Wm   = (const float*)d_in[13];
    const float* bm   = (const float*)d_in[14];
    const float* Wh   = (const float*)d_in[15];
    const float* bh   = (const float*)d_in[16];
    float* out = (float*)d_out;

    k0_const<<<1, 256>>>(cls, ln1w, ln1b, Wq, bq, Wk, bk, Wv, bv);

    dim3 g1a(P_, B_);
    k1a_tok_ln<<<g1a, 256>>>(x, Wp, ln1w, ln1b);

    dim3 g1b(NTOK / 64, H_);
    k1b_kv<<<g1b, 256>>>(Wk, bk, Wv, bv);

    k2_attn_ln2<<<B_, 256>>>(ln2w, ln2b);

    dim3 g3(D_ / 64, B_ / 64);
    gemm_k3<<<g3, 256>>>(Wm, bm);

    dim3 g4((OUT_ + 63) / 64, B_ / 64);
    gemm_k4<<<g4, 256>>>(Wh, bh);

    k5_softmax<<<B_, 256>>>(out);
}

// round 2
// speedup vs baseline: 4.8755x; 4.8755x over previous
#include <cuda_runtime.h>
#include <math.h>

#define B_    1024
#define D_    1024
#define H_    16
#define DH_   64
#define S_    50
#define P_    49
#define OUT_  1000
#define EPS_  1e-5f

// ---------------- scratch / tables (device globals) -------------------------
__device__ float g_pe[S_*D_];        // sinusoidal table
__device__ float g_pemean[S_], g_pe2[S_];
__device__ float g_gvec[S_*16];      // (1/1024) Wp[:,s].pe[pos]
__device__ float g_csum[16];         // (1/1024) column sums of Wp
__device__ float g_G[16*16];         // (1/1024) Wp^T Wp
__device__ float g_tok0c[D_];        // cls + pe0
__device__ float g_q0[D_], g_v0[D_];
__device__ float g_score0[H_];
__device__ float g_qk[D_];           // sum_e q0[h,e] Wk[h,e,d']
__device__ float g_sk[H_*16], g_spk[H_*S_], g_scw[H_], g_scb[H_];
__device__ float g_Mv[16*D_];        // [s][o]   o = h*64+e
__device__ float g_pv[S_*D_];        // [pos][o]
__device__ float g_cvw[D_], g_cvb[D_];
__device__ float g_tok0[(size_t)B_*D_];
__device__ float g_Z[(size_t)B_*D_];
__device__ float g_logits[(size_t)B_*OUT_];

// ---------------- helpers ----------------------------------------------------
__device__ __forceinline__ float pos_emb(int pos, int d) {
    float fd    = (float)(d & ~1);
    float denom = powf(10000.0f, fd * (1.0f / 1024.0f));
    float ang   = (float)pos / denom;
    return (d & 1) ? cosf(ang) : sinf(ang);
}

__device__ __forceinline__ float block_reduce_sum(float v, float* red) {
    int t = threadIdx.x;
    #pragma unroll
    for (int o = 16; o > 0; o >>= 1) v += __shfl_down_sync(0xffffffffu, v, o);
    if ((t & 31) == 0) red[t >> 5] = v;
    __syncthreads();
    if (t == 0) {
        float s = 0.f;
        int nw = blockDim.x >> 5;
        for (int i = 0; i < nw; i++) s += red[i];
        red[0] = s;
    }
    __syncthreads();
    float r = red[0];
    __syncthreads();
    return r;
}

__device__ __forceinline__ float block_reduce_max(float v, float* red) {
    int t = threadIdx.x;
    #pragma unroll
    for (int o = 16; o > 0; o >>= 1) v = fmaxf(v, __shfl_down_sync(0xffffffffu, v, o));
    if ((t & 31) == 0) red[t >> 5] = v;
    __syncthreads();
    if (t == 0) {
        float m = red[0];
        int nw = blockDim.x >> 5;
        for (int i = 1; i < nw; i++) m = fmaxf(m, red[i]);
        red[0] = m;
    }
    __syncthreads();
    float r = red[0];
    __syncthreads();
    return r;
}

// ---------------- K0a: pos-emb table + per-pos stats + gvec ------------------
__global__ __launch_bounds__(256) void k0_pe(const float* __restrict__ Wp) {
    int pos = blockIdx.x;
    __shared__ float pes[D_];
    __shared__ float red[32];
    __shared__ float partial[16][17];
    int t = threadIdx.x;

    for (int d = t; d < D_; d += 256) {
        float v = pos_emb(pos, d);
        pes[d] = v;
        g_pe[pos * D_ + d] = v;
    }
    __syncthreads();

    float s = 0.f, s2 = 0.f;
    for (int d = t; d < D_; d += 256) { float v = pes[d]; s += v; s2 += v * v; }
    float mean = block_reduce_sum(s, red) * (1.0f / D_);
    float m2   = block_reduce_sum(s2, red) * (1.0f / D_);
    if (t == 0) { g_pemean[pos] = mean; g_pe2[pos] = m2; }

    // gvec[pos,s] = (1/1024) sum_d Wp[d,s]*pe[pos,d]
    int sidx = t & 15, grp = t >> 4;
    float acc = 0.f;
    for (int d = grp; d < D_; d += 16)
        acc += Wp[d * 16 + sidx] * pes[d];
    partial[grp][sidx] = acc;
    __syncthreads();
    if (t < 16) {
        float a = 0.f;
        for (int g = 0; g < 16; g++) a += partial[g][t];
        g_gvec[pos * 16 + t] = a * (1.0f / D_);
    }
}

// ---------------- K0b: G (Wp^T Wp /1024) + csum -------------------------------
__global__ __launch_bounds__(256) void k0_stats(const float* __restrict__ Wp) {
    __shared__ float chunk[256][17];
    int t = threadIdx.x;
    int si = t >> 4, tj = t & 15;
    float acc = 0.f, accC = 0.f;
    for (int c = 0; c < 4; c++) {
        for (int idx = t; idx < 4096; idx += 256)
            chunk[idx >> 4][idx & 15] = Wp[(c * 256 + (idx >> 4)) * 16 + (idx & 15)];
        __syncthreads();
        for (int d = 0; d < 256; d++) acc += chunk[d][si] * chunk[d][tj];
        if (t < 16) for (int d = 0; d < 256; d++) accC += chunk[d][t];
        __syncthreads();
    }
    g_G[si * 16 + tj] = acc * (1.0f / D_);
    if (t < 16) g_csum[t] = accC * (1.0f / D_);
}

// ---------------- K0c: batch-invariant cls row + q0/v0/score0 + qk -----------
__global__ __launch_bounds__(256) void k0_cls(
    const float* __restrict__ cls, const float* __restrict__ ln1w, const float* __restrict__ ln1b,
    const float* __restrict__ Wq, const float* __restrict__ bq,
    const float* __restrict__ Wk, const float* __restrict__ bk,
    const float* __restrict__ Wv, const float* __restrict__ bv)
{
    __shared__ float tok[D_];
    __shared__ float n[D_];
    __shared__ float nq[D_];
    __shared__ float red[32];
    __shared__ float sacc[H_];
    int t = threadIdx.x;

    for (int d = t; d < D_; d += 256) tok[d] = cls[d] + g_pe[d];
    if (t < H_) sacc[t] = 0.f;
    __syncthreads();

    float s = 0.f;
    for (int d = t; d < D_; d += 256) s += tok[d];
    float mu = block_reduce_sum(s, red) * (1.0f / D_);
    float vs = 0.f;
    for (int d = t; d < D_; d += 256) { float dv = tok[d] - mu; vs += dv * dv; }
    float var  = block_reduce_sum(vs, red) * (1.0f / D_);
    float rstd = rsqrtf(var + EPS_);

    for (int d = t; d < D_; d += 256) {
        n[d] = (tok[d] - mu) * rstd * ln1w[d] + ln1b[d];
        g_tok0c[d] = tok[d];
    }
    __syncthreads();

    for (int o = t; o < D_; o += 256) {
        int h = o >> 6;
        const float* wq = Wq + h * 4096 + (o & 63) * 64;
        const float* wk = Wk + h * 4096 + (o & 63) * 64;
        const float* wv = Wv + h * 4096 + (o & 63) * 64;
        const float* nh = n + h * 64;
        float q = 0.f, k = 0.f, v = 0.f;
        #pragma unroll 8
        for (int d = 0; d < 64; d++) {
            float xv = nh[d];
            q += xv * wq[d]; k += xv * wk[d]; v += xv * wv[d];
        }
        q += bq[o]; k += bk[o]; v += bv[o];
        g_q0[o] = q; g_v0[o] = v; nq[o] = q;
        atomicAdd(&sacc[h], q * k);
    }
    __syncthreads();
    if (t < H_) g_score0[t] = 32.0f * sacc[t];

    // qk[h,d'] = sum_e q0[h,e] * Wk[h,e,d']
    for (int o = t; o < D_; o += 256) {
        int h = o >> 6, dp = o & 63;
        const float* wkh = Wk + h * 4096 + dp;
        const float* qh  = nq + h * 64;
        float a = 0.f;
        #pragma unroll 8
        for (int e = 0; e < 64; e++) a += qh[e] * wkh[e * 64];
        g_qk[o] = a;
    }
}

// ---------------- K0d: per-head tables (Mv, pv, cvw, cvb, sk, spk, scw, scb) -
__global__ __launch_bounds__(256) void k0_tabs(
    const float* __restrict__ Wp, const float* __restrict__ ln1w, const float* __restrict__ ln1b,
    const float* __restrict__ Wv, const float* __restrict__ bv,
    const float* __restrict__ bk)
{
    int h = blockIdx.x;
    __shared__ float Wvs[64][65];   // Wv[h,e,d']
    __shared__ float wpw[64][17];   // Wp[h*64+d', s] * ln1w
    __shared__ float pew[S_][65];   // pe[pos, h*64+d'] * ln1w
    __shared__ float qkr[64], w1h[64], b1h[64];
    int t = threadIdx.x;

    for (int idx = t; idx < 4096; idx += 256)
        Wvs[idx >> 6][idx & 63] = Wv[(size_t)h * 4096 + idx];
    for (int idx = t; idx < 1024; idx += 256) {
        int dp = idx >> 4, s = idx & 15;
        wpw[dp][s] = Wp[(h * 64 + dp) * 16 + s] * ln1w[h * 64 + dp];
    }
    for (int idx = t; idx < S_ * 64; idx += 256) {
        int pos = idx >> 6, dp = idx & 63;
        pew[pos][dp] = g_pe[pos * D_ + h * 64 + dp] * ln1w[h * 64 + dp];
    }
    if (t < 64) {
        qkr[t] = g_qk[h * 64 + t];
        w1h[t] = ln1w[h * 64 + t];
        b1h[t] = ln1b[h * 64 + t];
    }
    __syncthreads();

    // Mv[s][o]
    for (int idx = t; idx < 1024; idx += 256) {
        int e = idx >> 4, s = idx & 15;
        float a = 0.f;
        #pragma unroll 8
        for (int d = 0; d < 64; d++) a += Wvs[e][d] * wpw[d][s];
        g_Mv[s * D_ + h * 64 + e] = a;
    }
    // pv[pos][o]
    for (int idx = t; idx < 64 * S_; idx += 256) {
        int e = idx / S_, pos = idx % S_;
        float a = 0.f;
        #pragma unroll 8
        for (int d = 0; d < 64; d++) a += Wvs[e][d] * pew[pos][d];
        g_pv[pos * D_ + h * 64 + e] = a;
    }
    // cvw, cvb
    if (t < 64) {
        float aw = 0.f, ab = 0.f;
        #pragma unroll 8
        for (int d = 0; d < 64; d++) { aw += Wvs[t][d] * w1h[d]; ab += Wvs[t][d] * b1h[d]; }
        g_cvw[h * 64 + t] = aw;
        g_cvb[h * 64 + t] = ab + bv[h * 64 + t];
    }
    // sk[h,s]
    if (t >= 64 && t < 80) {
        int s = t - 64;
        float a = 0.f;
        for (int d = 0; d < 64; d++) a += qkr[d] * wpw[d][s];
        g_sk[h * 16 + s] = a;
    }
    // spk[h,pos]
    if (t >= 128 && t < 128 + S_) {
        int pos = t - 128;
        float a = 0.f;
        for (int d = 0; d < 64; d++) a += qkr[d] * pew[pos][d];
        g_spk[h * S_ + pos] = a;
    }
    // scw, scb
    if (t == 200) {
        float aw = 0.f, ab = 0.f;
        for (int d = 0; d < 64; d++) { aw += qkr[d] * w1h[d]; ab += qkr[d] * b1h[d]; }
        float qb = 0.f;
        for (int e = 0; e < 64; e++) qb += g_q0[h * 64 + e] * bk[h * 64 + e];
        g_scw[h] = aw;
        g_scb[h] = ab + qb;
    }
}

// ---------------- K_MAIN: per-batch scores+softmax+attn+LN2 ------------------
__global__ __launch_bounds__(256) void k_main(
    const float* __restrict__ x,
    const float* __restrict__ ln2w, const float* __restrict__ ln2b)
{
    int b = blockIdx.x;
    __shared__ float P16[P_][16];
    __shared__ float mu_s[P_], rs_s[P_];
    __shared__ float sc[H_][52];     // scores -> softmax weights
    __shared__ float wr[H_][52];     // w*rstd
    __shared__ float wp16[H_][16];
    __shared__ float A1[H_], A2[H_], w0[H_];
    __shared__ float tok[D_];
    __shared__ float Gs[256], sks[H_][16], csums[16];
    __shared__ float red[32];
    int t = threadIdx.x;

    // load image, rearranged into 49 patches of 16
    for (int idx = t; idx < 784; idx += 256) {
        int R = idx / 28, C = idx % 28;
        P16[(R >> 2) * 7 + (C >> 2)][(R & 3) * 4 + (C & 3)] = x[(size_t)b * 784 + idx];
    }
    // load small tables
    if (t < 256) Gs[t] = g_G[t];
    for (int idx = t; idx < 256; idx += 256) sks[idx >> 4][idx & 15] = g_sk[idx];
    if (t < 16) csums[t] = g_csum[t];
    __syncthreads();

    // per-token stats
    if (t < P_) {
        int p = t, pos = p + 1;
        const float* Pp = P16[p];
        float mu = g_pemean[pos];
        #pragma unroll
        for (int s = 0; s < 16; s++) mu += csums[s] * Pp[s];
        float e2 = g_pe2[pos];
        #pragma unroll
        for (int s = 0; s < 16; s++) {
            float acc = 0.f;
            #pragma unroll
            for (int u = 0; u < 16; u++) acc += Gs[s * 16 + u] * Pp[u];
            e2 += acc * Pp[s];
        }
        #pragma unroll
        for (int s = 0; s < 16; s++) e2 += 2.0f * g_gvec[pos * 16 + s] * Pp[s];
        float var = e2 - mu * mu;
        mu_s[p] = mu;
        rs_s[p] = rsqrtf(var + EPS_);
    }
    __syncthreads();

    // scores
    for (int idx = t; idx < H_ * P_; idx += 256) {
        int h = idx / P_, p = idx % P_, pos = p + 1;
        const float* Pp = P16[p];
        float a = 0.f;
        #pragma unroll
        for (int s = 0; s < 16; s++) a += sks[h][s] * Pp[s];
        float sco = rs_s[p] * (a + g_spk[h * S_ + pos] - mu_s[p] * g_scw[h]) + g_scb[h];
        sc[h][p + 1] = 32.0f * sco;
    }
    if (t < H_) sc[t][0] = g_score0[t];
    __syncthreads();

    // softmax per head
    if (t < H_) {
        int h = t;
        float m = sc[h][0];
        for (int s = 1; s < S_; s++) m = fmaxf(m, sc[h][s]);
        float sum = 0.f;
        for (int s = 0; s < S_; s++) { float e = expf(sc[h][s] - m); sc[h][s] = e; sum += e; }
        float inv = 1.f / sum;
        for (int s = 0; s < S_; s++) sc[h][s] *= inv;
        w0[h] = sc[h][0];
        A2[h] = 1.0f - sc[h][0];
    }
    __syncthreads();

    // wr = w * rstd
    for (int idx = t; idx < H_ * P_; idx += 256) {
        int h = idx / P_, p = idx % P_;
        wr[h][p] = sc[h][p + 1] * rs_s[p];
    }
    __syncthreads();

    // A1, wp16
    if (t < H_) {
        float a = 0.f;
        for (int p = 0; p < P_; p++) a += wr[t][p] * mu_s[p];
        A1[t] = a;
    }
    {
        int h = t >> 4, s = t & 15;
        float a = 0.f;
        for (int p = 0; p < P_; p++) a += wr[h][p] * P16[p][s];
        wp16[h][s] = a;
    }
    __syncthreads();

    // attn + residual
    for (int o = t; o < D_; o += 256) {
        int h = o >> 6;
        float a = w0[h] * g_v0[o];
        #pragma unroll
        for (int s = 0; s < 16; s++) a += g_Mv[s * D_ + o] * wp16[h][s];
        #pragma unroll 7
        for (int p = 0; p < P_; p++) a += wr[h][p] * g_pv[(p + 1) * D_ + o];
        a += -g_cvw[o] * A1[h] + g_cvb[o] * A2[h];
        float tk = g_tok0c[o] + a;
        tok[o] = tk;
        g_tok0[(size_t)b * D_ + o] = tk;
    }
    __syncthreads();

    // LN2
    float s = 0.f;
    for (int d = t; d < D_; d += 256) s += tok[d];
    float mu = block_reduce_sum(s, red) * (1.0f / D_);
    float vs = 0.f;
    for (int d = t; d < D_; d += 256) { float dv = tok[d] - mu; vs += dv * dv; }
    float var  = block_reduce_sum(vs, red) * (1.0f / D_);
    float rstd = rsqrtf(var + EPS_);
    for (int d = t; d < D_; d += 256)
        g_Z[(size_t)b * D_ + d] = (tok[d] - mu) * rstd * ln2w[d] + ln2b[d];
}

// ---------------- 128x128x16 fp32 NT SGEMM (8x8 per thread) ------------------
__device__ __forceinline__ void sgemm128_body(
    const float* __restrict__ A, const float* __restrict__ Bm,
    const float* __restrict__ addm, const float* __restrict__ bias,
    float* __restrict__ C, int M, int N, int K, int addFlag)
{
    __shared__ float As[16][128];
    __shared__ float Bs[16][128];
    int t = threadIdx.x;
    int tx = t & 15, ty = t >> 4;
    int m0 = blockIdx.y * 128, n0 = blockIdx.x * 128;
    float acc[8][8] = {};

    for (int k0 = 0; k0 < K; k0 += 16) {
        #pragma unroll
        for (int l = 0; l < 2; l++) {
            int idx = t + l * 256;
            int mm = idx >> 2, kq = (idx & 3) * 4;
            float4 va = *(const float4*)&A[(size_t)(m0 + mm) * K + k0 + kq];
            As[kq + 0][mm] = va.x; As[kq + 1][mm] = va.y;
            As[kq + 2][mm] = va.z; As[kq + 3][mm] = va.w;
            int row = n0 + mm;
            float4 vb = make_float4(0.f, 0.f, 0.f, 0.f);
            if (row < N) vb = *(const float4*)&Bm[(size_t)row * K + k0 + kq];
            Bs[kq + 0][mm] = vb.x; Bs[kq + 1][mm] = vb.y;
            Bs[kq + 2][mm] = vb.z; Bs[kq + 3][mm] = vb.w;
        }
        __syncthreads();
        #pragma unroll
        for (int kk = 0; kk < 16; kk++) {
            float4 a0 = *(const float4*)&As[kk][ty * 8];
            float4 a1 = *(const float4*)&As[kk][ty * 8 + 4];
            float4 b0 = *(const float4*)&Bs[kk][tx * 8];
            float4 b1 = *(const float4*)&Bs[kk][tx * 8 + 4];
            float av[8] = {a0.x, a0.y, a0.z, a0.w, a1.x, a1.y, a1.z, a1.w};
            float bv[8] = {b0.x, b0.y, b0.z, b0.w, b1.x, b1.y, b1.z, b1.w};
            #pragma unroll
            for (int i = 0; i < 8; i++)
                #pragma unroll
                for (int j = 0; j < 8; j++)
                    acc[i][j] += av[i] * bv[j];
        }
        __syncthreads();
    }

    #pragma unroll
    for (int i = 0; i < 8; i++) {
        int m = m0 + ty * 8 + i;
        #pragma unroll
        for (int j = 0; j < 8; j++) {
            int n = n0 + tx * 8 + j;
            if (n < N) {
                float v = acc[i][j] + bias[n];
                if (addFlag) v += addm[(size_t)m * N + n];
                C[(size_t)m * N + n] = v;
            }
        }
    }
}

__global__ __launch_bounds__(256) void gemm_k3(const float* __restrict__ Wm,
                                               const float* __restrict__ bm) {
    sgemm128_body(g_Z, Wm, g_tok0, bm, g_tok0, B_, D_, D_, 1);
}

__global__ __launch_bounds__(256) void gemm_k4(const float* __restrict__ Wh,
                                               const float* __restrict__ bh) {
    sgemm128_body(g_tok0, Wh, nullptr, bh, g_logits, B_, OUT_, D_, 0);
}

// ---------------- K5: row softmax over 1000 logits ---------------------------
__global__ __launch_bounds__(256) void k5_softmax(float* __restrict__ out) {
    int b = blockIdx.x;
    __shared__ float red[32];
    int t = threadIdx.x;
    const float* lg = g_logits + (size_t)b * OUT_;

    float m = -1e30f;
    for (int o = t; o < OUT_; o += 256) m = fmaxf(m, lg[o]);
    m = block_reduce_max(m, red);

    float s = 0.f;
    for (int o = t; o < OUT_; o += 256) s += expf(lg[o] - m);
    float sum = block_reduce_sum(s, red);
    float inv = 1.f / sum;

    float* ob = out + (size_t)b * OUT_;
    for (int o = t; o < OUT_; o += 256) ob[o] = expf(lg[o] - m) * inv;
}

// ---------------- launch ------------------------------------------------------
extern "C" void kernel_launch(void* const* d_in, const int* in_sizes, int n_in,
                              void* d_out, int out_size) {
    const float* x    = (const float*)d_in[0];
    const float* cls  = (const float*)d_in[1];
    const float* Wp   = (const float*)d_in[2];
    const float* ln1w = (const float*)d_in[3];
    const float* ln1b = (const float*)d_in[4];
    const float* Wq   = (const float*)d_in[5];
    const float* bq   = (const float*)d_in[6];
    const float* Wk   = (const float*)d_in[7];
    const float* bk   = (const float*)d_in[8];
    const float* Wv   = (const float*)d_in[9];
    const float* bv   = (const float*)d_in[10];
    const float* ln2w = (const float*)d_in[11];
    const float* ln2b = (const float*)d_in[12];
    const float* Wm   = (const float*)d_in[13];
    const float* bm   = (const float*)d_in[14];
    const float* Wh   = (const float*)d_in[15];
    const float* bh   = (const float*)d_in[16];
    float* out = (float*)d_out;

    k0_pe<<<S_, 256>>>(Wp);
    k0_stats<<<1, 256>>>(Wp);
    k0_cls<<<1, 256>>>(cls, ln1w, ln1b, Wq, bq, Wk, bk, Wv, bv);
    k0_tabs<<<H_, 256>>>(Wp, ln1w, ln1b, Wv, bv, bk);

    k_main<<<B_, 256>>>(x, ln2w, ln2b);

    dim3 g3(D_ / 128, B_ / 128);
    gemm_k3<<<g3, 256>>>(Wm, bm);

    dim3 g4((OUT_ + 127) / 128, B_ / 128);
    gemm_k4<<<g4, 256>>>(Wh, bh);

    k5_softmax<<<B_, 256>>>(out);
}

// round 4
// speedup vs baseline: 6.4369x; 1.3203x over previous
#include <cuda_runtime.h>
#include <cuda_bf16.h>
#include <cstdint>
#include <math.h>

#define B_    1024
#define D_    1024
#define H_    16
#define S_    50
#define P_    49
#define OUT_  1000
#define EPS_  1e-5f
#define KP_   3072          // bf16x3 expanded K
#define NCH_  96            // KP_/32

// ---------------- scratch / tables (device globals) -------------------------
__device__ float g_pe[S_*D_];
__device__ float g_pemean[S_], g_pe2[S_];
__device__ float g_gvec[S_*16];
__device__ float g_csum[16];
__device__ float g_G[16*16];
__device__ float g_tok0c[D_];
__device__ float g_q0[D_], g_v0[D_];
__device__ float g_score0[H_];
__device__ float g_qk[D_];
__device__ float g_sk[H_*16], g_spk[H_*S_], g_scw[H_], g_scb[H_];
__device__ float g_Mv[16*D_];
__device__ float g_pv[S_*D_];
__device__ float g_cvw[D_], g_cvb[D_];
__device__ float g_tok0[(size_t)B_*D_];                 // attn residual (pre-MLP)
__device__ float g_logits[(size_t)B_*OUT_];
__device__ __nv_bfloat16 g_Zp[(size_t)B_*KP_];          // Z'  [hi|hi|lo]
__device__ __nv_bfloat16 g_Yp[(size_t)B_*KP_];          // Y'  [hi|hi|lo]
__device__ __nv_bfloat16 g_Wmp[(size_t)1024*KP_];       // Wm' [hi|lo|hi]
__device__ __nv_bfloat16 g_Whp[(size_t)1024*KP_];       // Wh' [hi|lo|hi] (padded rows)

// ---------------- PTX helpers ------------------------------------------------
__device__ __forceinline__ uint32_t smem_to_u32(const void* p) {
    uint32_t a;
    asm("{ .reg .u64 tmp; cvta.to.shared.u64 tmp, %1; cvt.u32.u64 %0, tmp; }" : "=r"(a) : "l"(p));
    return a;
}
#define LDMATRIX_X4(r0, r1, r2, r3, addr) \
    asm volatile("ldmatrix.sync.aligned.m8n8.x4.shared.b16 {%0,%1,%2,%3}, [%4];" \
        : "=r"(r0), "=r"(r1), "=r"(r2), "=r"(r3) : "r"(addr))
#define MMA_BF16(d, a, b) \
    asm volatile("mma.sync.aligned.m16n8k16.row.col.f32.bf16.bf16.f32 " \
        "{%0,%1,%2,%3}, {%4,%5,%6,%7}, {%8,%9}, {%0,%1,%2,%3};" \
        : "+f"((d)[0]), "+f"((d)[1]), "+f"((d)[2]), "+f"((d)[3]) \
        : "r"((a)[0]), "r"((a)[1]), "r"((a)[2]), "r"((a)[3]), "r"((b)[0]), "r"((b)[1]))

// ---------------- math helpers ------------------------------------------------
__device__ __forceinline__ float pos_emb(int pos, int d) {
    float fd    = (float)(d & ~1);
    float denom = powf(10000.0f, fd * (1.0f / 1024.0f));
    float ang   = (float)pos / denom;
    return (d & 1) ? cosf(ang) : sinf(ang);
}
__device__ __forceinline__ float block_reduce_sum(float v, float* red) {
    int t = threadIdx.x;
    #pragma unroll
    for (int o = 16; o > 0; o >>= 1) v += __shfl_down_sync(0xffffffffu, v, o);
    if ((t & 31) == 0) red[t >> 5] = v;
    __syncthreads();
    if (t == 0) {
        float s = 0.f; int nw = blockDim.x >> 5;
        for (int i = 0; i < nw; i++) s += red[i];
        red[0] = s;
    }
    __syncthreads();
    float r = red[0];
    __syncthreads();
    return r;
}
__device__ __forceinline__ float block_reduce_max(float v, float* red) {
    int t = threadIdx.x;
    #pragma unroll
    for (int o = 16; o > 0; o >>= 1) v = fmaxf(v, __shfl_down_sync(0xffffffffu, v, o));
    if ((t & 31) == 0) red[t >> 5] = v;
    __syncthreads();
    if (t == 0) {
        float m = red[0]; int nw = blockDim.x >> 5;
        for (int i = 1; i < nw; i++) m = fmaxf(m, red[i]);
        red[0] = m;
    }
    __syncthreads();
    float r = red[0];
    __syncthreads();
    return r;
}
__device__ __forceinline__ void split_bf16(float x, __nv_bfloat16& hi, __nv_bfloat16& lo) {
    hi = __float2bfloat16(x);
    lo = __float2bfloat16(x - __bfloat162float(hi));
}

// ---------------- conv_w: fp32 weight -> bf16x3 B-layout [hi|lo|hi] -----------
__global__ __launch_bounds__(256) void conv_w(const float* __restrict__ W, int rows, int which) {
    size_t i = (size_t)blockIdx.x * 256 + threadIdx.x;   // over 1024*1024
    int r = (int)(i >> 10), k = (int)(i & 1023);
    float v = (r < rows) ? W[(size_t)r * 1024 + k] : 0.f;
    __nv_bfloat16 hi, lo; split_bf16(v, hi, lo);
    __nv_bfloat16* dst = which ? g_Whp : g_Wmp;
    dst[(size_t)r * KP_ + k]        = hi;
    dst[(size_t)r * KP_ + 1024 + k] = lo;
    dst[(size_t)r * KP_ + 2048 + k] = hi;
}

// ---------------- K0a: pe table + per-pos stats + gvec (+stats block) ---------
__global__ __launch_bounds__(256) void k0_pe(const float* __restrict__ Wp) {
    __shared__ float pes[D_];
    __shared__ float red[32];
    __shared__ float partial[16][17];
    __shared__ float chunk[256][17];
    int t = threadIdx.x;

    if (blockIdx.x == 50) {   // Wp^T Wp /1024 + colsums
        int si = t >> 4, tj = t & 15;
        float acc = 0.f, accC = 0.f;
        for (int c = 0; c < 4; c++) {
            for (int idx = t; idx < 4096; idx += 256)
                chunk[idx >> 4][idx & 15] = Wp[(c * 256 + (idx >> 4)) * 16 + (idx & 15)];
            __syncthreads();
            for (int d = 0; d < 256; d++) acc += chunk[d][si] * chunk[d][tj];
            if (t < 16) for (int d = 0; d < 256; d++) accC += chunk[d][t];
            __syncthreads();
        }
        g_G[si * 16 + tj] = acc * (1.0f / D_);
        if (t < 16) g_csum[t] = accC * (1.0f / D_);
        return;
    }

    int pos = blockIdx.x;
    for (int d = t; d < D_; d += 256) {
        float v = pos_emb(pos, d);
        pes[d] = v;
        g_pe[pos * D_ + d] = v;
    }
    __syncthreads();
    float s = 0.f, s2 = 0.f;
    for (int d = t; d < D_; d += 256) { float v = pes[d]; s += v; s2 += v * v; }
    float mean = block_reduce_sum(s, red) * (1.0f / D_);
    float m2   = block_reduce_sum(s2, red) * (1.0f / D_);
    if (t == 0) { g_pemean[pos] = mean; g_pe2[pos] = m2; }

    int sidx = t & 15, grp = t >> 4;
    float acc = 0.f;
    for (int d = grp; d < D_; d += 16) acc += Wp[d * 16 + sidx] * pes[d];
    partial[grp][sidx] = acc;
    __syncthreads();
    if (t < 16) {
        float a = 0.f;
        for (int g = 0; g < 16; g++) a += partial[g][t];
        g_gvec[pos * 16 + t] = a * (1.0f / D_);
    }
}

// ---------------- K0c: cls row constants --------------------------------------
__global__ __launch_bounds__(256) void k0_cls(
    const float* __restrict__ cls, const float* __restrict__ ln1w, const float* __restrict__ ln1b,
    const float* __restrict__ Wq, const float* __restrict__ bq,
    const float* __restrict__ Wk, const float* __restrict__ bk,
    const float* __restrict__ Wv, const float* __restrict__ bv)
{
    __shared__ float tok[D_];
    __shared__ float n[D_];
    __shared__ float nq[D_];
    __shared__ float red[32];
    __shared__ float sacc[H_];
    int t = threadIdx.x;

    for (int d = t; d < D_; d += 256) tok[d] = cls[d] + g_pe[d];
    if (t < H_) sacc[t] = 0.f;
    __syncthreads();

    float s = 0.f;
    for (int d = t; d < D_; d += 256) s += tok[d];
    float mu = block_reduce_sum(s, red) * (1.0f / D_);
    float vs = 0.f;
    for (int d = t; d < D_; d += 256) { float dv = tok[d] - mu; vs += dv * dv; }
    float var  = block_reduce_sum(vs, red) * (1.0f / D_);
    float rstd = rsqrtf(var + EPS_);

    for (int d = t; d < D_; d += 256) {
        n[d] = (tok[d] - mu) * rstd * ln1w[d] + ln1b[d];
        g_tok0c[d] = tok[d];
    }
    __syncthreads();

    for (int o = t; o < D_; o += 256) {
        int h = o >> 6;
        const float* wq = Wq + h * 4096 + (o & 63) * 64;
        const float* wk = Wk + h * 4096 + (o & 63) * 64;
        const float* wv = Wv + h * 4096 + (o & 63) * 64;
        const float* nh = n + h * 64;
        float q = 0.f, k = 0.f, v = 0.f;
        #pragma unroll 8
        for (int d = 0; d < 64; d++) {
            float xv = nh[d];
            q += xv * wq[d]; k += xv * wk[d]; v += xv * wv[d];
        }
        q += bq[o]; k += bk[o]; v += bv[o];
        g_q0[o] = q; g_v0[o] = v; nq[o] = q;
        atomicAdd(&sacc[h], q * k);
    }
    __syncthreads();
    if (t < H_) g_score0[t] = 32.0f * sacc[t];

    for (int o = t; o < D_; o += 256) {
        int h = o >> 6, dp = o & 63;
        const float* wkh = Wk + h * 4096 + dp;
        const float* qh  = nq + h * 64;
        float a = 0.f;
        #pragma unroll 8
        for (int e = 0; e < 64; e++) a += qh[e] * wkh[e * 64];
        g_qk[o] = a;
    }
}

// ---------------- K0d: per-head tables, 4-way split per head ------------------
__global__ __launch_bounds__(256) void k0_tabs(
    const float* __restrict__ Wp, const float* __restrict__ ln1w, const float* __restrict__ ln1b,
    const float* __restrict__ Wv, const float* __restrict__ bv,
    const float* __restrict__ bk)
{
    int h = blockIdx.x >> 2, q = blockIdx.x & 3;
    __shared__ float Wvs[64][65];
    __shared__ float wpw[64][17];
    __shared__ float pew[S_][65];
    __shared__ float qkr[64], w1h[64], b1h[64];
    int t = threadIdx.x;

    for (int idx = t; idx < 4096; idx += 256)
        Wvs[idx >> 6][idx & 63] = Wv[(size_t)h * 4096 + idx];
    for (int idx = t; idx < 1024; idx += 256) {
        int dp = idx >> 4, s = idx & 15;
        wpw[dp][s] = Wp[(h * 64 + dp) * 16 + s] * ln1w[h * 64 + dp];
    }
    for (int idx = t; idx < S_ * 64; idx += 256) {
        int pos = idx >> 6, dp = idx & 63;
        pew[pos][dp] = g_pe[pos * D_ + h * 64 + dp] * ln1w[h * 64 + dp];
    }
    if (t < 64) {
        qkr[t] = g_qk[h * 64 + t];
        w1h[t] = ln1w[h * 64 + t];
        b1h[t] = ln1b[h * 64 + t];
    }
    __syncthreads();

    {   // Mv quarter: 256 outputs
        int idx = q * 256 + t;
        int e = idx >> 4, s = idx & 15;
        float a = 0.f;
        #pragma unroll 8
        for (int d = 0; d < 64; d++) a += Wvs[e][d] * wpw[d][s];
        g_Mv[s * D_ + h * 64 + e] = a;
    }
    // pv quarter: 800 of 3200
    for (int idx = q * 800 + t; idx < (q + 1) * 800 && idx < 3200; idx += 256) {
        int e = idx / S_, pos = idx % S_;
        float a = 0.f;
        #pragma unroll 8
        for (int d = 0; d < 64; d++) a += Wvs[e][d] * pew[pos][d];
        g_pv[pos * D_ + h * 64 + e] = a;
    }
    if (q == 0) {
        if (t < 64) {
            float aw = 0.f, ab = 0.f;
            #pragma unroll 8
            for (int d = 0; d < 64; d++) { aw += Wvs[t][d] * w1h[d]; ab += Wvs[t][d] * b1h[d]; }
            g_cvw[h * 64 + t] = aw;
            g_cvb[h * 64 + t] = ab + bv[h * 64 + t];
        }
        if (t >= 64 && t < 80) {
            int s = t - 64;
            float a = 0.f;
            for (int d = 0; d < 64; d++) a += qkr[d] * wpw[d][s];
            g_sk[h * 16 + s] = a;
        }
        if (t >= 128 && t < 128 + S_) {
            int pos = t - 128;
            float a = 0.f;
            for (int d = 0; d < 64; d++) a += qkr[d] * pew[pos][d];
            g_spk[h * S_ + pos] = a;
        }
        if (t == 200) {
            float aw = 0.f, ab = 0.f;
            for (int d = 0; d < 64; d++) { aw += qkr[d] * w1h[d]; ab += qkr[d] * b1h[d]; }
            float qb = 0.f;
            for (int e = 0; e < 64; e++) qb += g_q0[h * 64 + e] * bk[h * 64 + e];
            g_scw[h] = aw;
            g_scb[h] = ab + qb;
        }
    }
}

// ---------------- K_MAIN: per-batch attn + LN2 -> Z' bf16x3 -------------------
__global__ __launch_bounds__(256) void k_main(
    const float* __restrict__ x,
    const float* __restrict__ ln2w, const float* __restrict__ ln2b)
{
    int b = blockIdx.x;
    __shared__ float P16[P_][16];
    __shared__ float mu_s[P_], rs_s[P_];
    __shared__ float sc[H_][52];
    __shared__ float wr[H_][52];
    __shared__ float wp16[H_][16];
    __shared__ float A1[H_], A2[H_], w0[H_];
    __shared__ float tok[D_];
    __shared__ float Gs[256], sks[H_][16], csums[16];
    __shared__ float red[32];
    int t = threadIdx.x;

    for (int idx = t; idx < 784; idx += 256) {
        int R = idx / 28, C = idx % 28;
        P16[(R >> 2) * 7 + (C >> 2)][(R & 3) * 4 + (C & 3)] = x[(size_t)b * 784 + idx];
    }
    if (t < 256) Gs[t] = g_G[t];
    for (int idx = t; idx < 256; idx += 256) sks[idx >> 4][idx & 15] = g_sk[idx];
    if (t < 16) csums[t] = g_csum[t];
    __syncthreads();

    if (t < P_) {
        int p = t, pos = p + 1;
        const float* Pp = P16[p];
        float mu = g_pemean[pos];
        #pragma unroll
        for (int s = 0; s < 16; s++) mu += csums[s] * Pp[s];
        float e2 = g_pe2[pos];
        #pragma unroll
        for (int s = 0; s < 16; s++) {
            float acc = 0.f;
            #pragma unroll
            for (int u = 0; u < 16; u++) acc += Gs[s * 16 + u] * Pp[u];
            e2 += acc * Pp[s];
        }
        #pragma unroll
        for (int s = 0; s < 16; s++) e2 += 2.0f * g_gvec[pos * 16 + s] * Pp[s];
        float var = e2 - mu * mu;
        mu_s[p] = mu;
        rs_s[p] = rsqrtf(var + EPS_);
    }
    __syncthreads();

    for (int idx = t; idx < H_ * P_; idx += 256) {
        int h = idx / P_, p = idx % P_, pos = p + 1;
        const float* Pp = P16[p];
        float a = 0.f;
        #pragma unroll
        for (int s = 0; s < 16; s++) a += sks[h][s] * Pp[s];
        float sco = rs_s[p] * (a + g_spk[h * S_ + pos] - mu_s[p] * g_scw[h]) + g_scb[h];
        sc[h][p + 1] = 32.0f * sco;
    }
    if (t < H_) sc[t][0] = g_score0[t];
    __syncthreads();

    if (t < H_) {
        int h = t;
        float m = sc[h][0];
        for (int s = 1; s < S_; s++) m = fmaxf(m, sc[h][s]);
        float sum = 0.f;
        for (int s = 0; s < S_; s++) { float e = expf(sc[h][s] - m); sc[h][s] = e; sum += e; }
        float inv = 1.f / sum;
        for (int s = 0; s < S_; s++) sc[h][s] *= inv;
        w0[h] = sc[h][0];
        A2[h] = 1.0f - sc[h][0];
    }
    __syncthreads();

    for (int idx = t; idx < H_ * P_; idx += 256) {
        int h = idx / P_, p = idx % P_;
        wr[h][p] = sc[h][p + 1] * rs_s[p];
    }
    __syncthreads();

    if (t < H_) {
        float a = 0.f;
        for (int p = 0; p < P_; p++) a += wr[t][p] * mu_s[p];
        A1[t] = a;
    }
    {
        int h = t >> 4, s = t & 15;
        float a = 0.f;
        for (int p = 0; p < P_; p++) a += wr[h][p] * P16[p][s];
        wp16[h][s] = a;
    }
    __syncthreads();

    for (int o = t; o < D_; o += 256) {
        int h = o >> 6;
        float a = w0[h] * g_v0[o];
        #pragma unroll
        for (int s = 0; s < 16; s++) a += g_Mv[s * D_ + o] * wp16[h][s];
        #pragma unroll 7
        for (int p = 0; p < P_; p++) a += wr[h][p] * g_pv[(p + 1) * D_ + o];
        a += -g_cvw[o] * A1[h] + g_cvb[o] * A2[h];
        float tk = g_tok0c[o] + a;
        tok[o] = tk;
        g_tok0[(size_t)b * D_ + o] = tk;
    }
    __syncthreads();

    float s = 0.f;
    for (int d = t; d < D_; d += 256) s += tok[d];
    float mu = block_reduce_sum(s, red) * (1.0f / D_);
    float vs = 0.f;
    for (int d = t; d < D_; d += 256) { float dv = tok[d] - mu; vs += dv * dv; }
    float var  = block_reduce_sum(vs, red) * (1.0f / D_);
    float rstd = rsqrtf(var + EPS_);
    for (int d = t; d < D_; d += 256) {
        float z = (tok[d] - mu) * rstd * ln2w[d] + ln2b[d];
        __nv_bfloat16 hi, lo; split_bf16(z, hi, lo);
        g_Zp[(size_t)b * KP_ + d]        = hi;
        g_Zp[(size_t)b * KP_ + 1024 + d] = hi;
        g_Zp[(size_t)b * KP_ + 2048 + d] = lo;
    }
}

// ---------------- HMMA bf16 GEMM: C(128x128) = A'(128xKP) . B'(128xKP)^T ------
// 8 warps: warp_m = wid>>2 (64 rows), warp_n = wid&3 (32 cols); 4x4 m16n8 tiles.
// MODE 0: k3  (C = acc + bm + g_tok0  -> Y' bf16x3 into g_Yp)
// MODE 1: k4  (C = acc + bh           -> g_logits fp32, n<1000)
template<int MODE>
__global__ __launch_bounds__(256) void gemm_tc(const float* __restrict__ bias) {
    __shared__ __nv_bfloat16 As[128][40];   // 32 K + 8 pad (80B row stride)
    __shared__ __nv_bfloat16 Bs[128][40];
    int t = threadIdx.x;
    int wid = t >> 5, lane = t & 31;
    int warp_m = wid >> 2, warp_n = wid & 3;
    int m0 = blockIdx.y * 128, n0 = blockIdx.x * 128;

    const __nv_bfloat16* Ag = ((MODE == 0) ? g_Zp : g_Yp) + (size_t)m0 * KP_;
    const __nv_bfloat16* Bg = ((MODE == 0) ? g_Wmp : g_Whp) + (size_t)n0 * KP_;

    float acc[4][4][4];
    #pragma unroll
    for (int i = 0; i < 4; i++)
        #pragma unroll
        for (int j = 0; j < 4; j++)
            #pragma unroll
            for (int e = 0; e < 4; e++) acc[i][j][e] = 0.f;

    uint32_t As_base = smem_to_u32(&As[0][0]);
    uint32_t Bs_base = smem_to_u32(&Bs[0][0]);

    // precompute ldmatrix lane addressing
    int a_row = warp_m * 64 + (lane & 15);       // + i*16
    int a_col8 = (lane >> 4) * 8;                // + ks*16
    int b_quad = lane >> 3;
    int b_tile = b_quad >> 1;                    // 0/1 within pair
    int b_seg8 = (b_quad & 1) * 8;               // + ks*16
    int b_row = warp_n * 32 + (lane & 7);        // + (jp*2 + b_tile)*8

    for (int ch = 0; ch < NCH_; ch++) {
        int k0 = ch * 32;
        #pragma unroll
        for (int it = 0; it < 2; it++) {
            int idx = t + it * 256;
            int r = idx >> 2, seg = (idx & 3) * 8;
            *(uint4*)&As[r][seg] = *(const uint4*)(Ag + (size_t)r * KP_ + k0 + seg);
            *(uint4*)&Bs[r][seg] = *(const uint4*)(Bg + (size_t)r * KP_ + k0 + seg);
        }
        __syncthreads();
        #pragma unroll
        for (int ks = 0; ks < 2; ks++) {
            uint32_t a[4][4];
            #pragma unroll
            for (int i = 0; i < 4; i++) {
                uint32_t addr = As_base + (uint32_t)(((a_row + i * 16) * 40 + ks * 16 + a_col8) * 2);
                LDMATRIX_X4(a[i][0], a[i][1], a[i][2], a[i][3], addr);
            }
            uint32_t bfr[4][2];
            #pragma unroll
            for (int jp = 0; jp < 2; jp++) {
                uint32_t addr = Bs_base + (uint32_t)(((b_row + (jp * 2 + b_tile) * 8) * 40 + ks * 16 + b_seg8) * 2);
                uint32_t r0, r1, r2, r3;
                LDMATRIX_X4(r0, r1, r2, r3, addr);
                bfr[jp * 2][0] = r0; bfr[jp * 2][1] = r1;
                bfr[jp * 2 + 1][0] = r2; bfr[jp * 2 + 1][1] = r3;
            }
            #pragma unroll
            for (int i = 0; i < 4; i++)
                #pragma unroll
                for (int j = 0; j < 4; j++)
                    MMA_BF16(acc[i][j], a[i], bfr[j]);
        }
        __syncthreads();
    }

    // epilogue
    int r4 = lane >> 2, c2 = (lane & 3) * 2;
    #pragma unroll
    for (int i = 0; i < 4; i++) {
        #pragma unroll
        for (int j = 0; j < 4; j++) {
            int n = n0 + warp_n * 32 + j * 8 + c2;
            #pragma unroll
            for (int half = 0; half < 2; half++) {
                int m = m0 + warp_m * 64 + i * 16 + r4 + half * 8;
                float v0 = acc[i][j][half * 2 + 0];
                float v1 = acc[i][j][half * 2 + 1];
                if (MODE == 0) {
                    v0 += bias[n]     + g_tok0[(size_t)m * D_ + n];
                    v1 += bias[n + 1] + g_tok0[(size_t)m * D_ + n + 1];
                    __nv_bfloat16 h0, l0, h1, l1;
                    split_bf16(v0, h0, l0); split_bf16(v1, h1, l1);
                    __nv_bfloat162 hp; hp.x = h0; hp.y = h1;
                    __nv_bfloat162 lp; lp.x = l0; lp.y = l1;
                    *(__nv_bfloat162*)&g_Yp[(size_t)m * KP_ + n]        = hp;
                    *(__nv_bfloat162*)&g_Yp[(size_t)m * KP_ + 1024 + n] = hp;
                    *(__nv_bfloat162*)&g_Yp[(size_t)m * KP_ + 2048 + n] = lp;
                } else {
                    if (n < OUT_)     g_logits[(size_t)m * OUT_ + n]     = v0 + bias[n];
                    if (n + 1 < OUT_) g_logits[(size_t)m * OUT_ + n + 1] = v1 + bias[n + 1];
                }
            }
        }
    }
}

// ---------------- K5: row softmax over 1000 logits -----------------------------
__global__ __launch_bounds__(256) void k5_softmax(float* __restrict__ out) {
    int b = blockIdx.x;
    __shared__ float red[32];
    int t = threadIdx.x;
    const float* lg = g_logits + (size_t)b * OUT_;

    float m = -1e30f;
    for (int o = t; o < OUT_; o += 256) m = fmaxf(m, lg[o]);
    m = block_reduce_max(m, red);

    float s = 0.f;
    for (int o = t; o < OUT_; o += 256) s += expf(lg[o] - m);
    float sum = block_reduce_sum(s, red);
    float inv = 1.f / sum;

    float* ob = out + (size_t)b * OUT_;
    for (int o = t; o < OUT_; o += 256) ob[o] = expf(lg[o] - m) * inv;
}

// ---------------- launch --------------------------------------------------------
extern "C" void kernel_launch(void* const* d_in, const int* in_sizes, int n_in,
                              void* d_out, int out_size) {
    const float* x    = (const float*)d_in[0];
    const float* cls  = (const float*)d_in[1];
    const float* Wp   = (const float*)d_in[2];
    const float* ln1w = (const float*)d_in[3];
    const float* ln1b = (const float*)d_in[4];
    const float* Wq   = (const float*)d_in[5];
    const float* bq   = (const float*)d_in[6];
    const float* Wk   = (const float*)d_in[7];
    const float* bk   = (const float*)d_in[8];
    const float* Wv   = (const float*)d_in[9];
    const float* bv   = (const float*)d_in[10];
    const float* ln2w = (const float*)d_in[11];
    const float* ln2b = (const float*)d_in[12];
    const float* Wm   = (const float*)d_in[13];
    const float* bm   = (const float*)d_in[14];
    const float* Wh   = (const float*)d_in[15];
    const float* bh   = (const float*)d_in[16];
    float* out = (float*)d_out;

    conv_w<<<4096, 256>>>(Wm, 1024, 0);
    conv_w<<<4096, 256>>>(Wh, OUT_, 1);
    k0_pe<<<51, 256>>>(Wp);
    k0_cls<<<1, 256>>>(cls, ln1w, ln1b, Wq, bq, Wk, bk, Wv, bv);
    k0_tabs<<<64, 256>>>(Wp, ln1w, ln1b, Wv, bv, bk);

    k_main<<<B_, 256>>>(x, ln2w, ln2b);

    dim3 g(8, 8);
    gemm_tc<0><<<g, 256>>>(bm);
    gemm_tc<1><<<g, 256>>>(bh);

    k5_softmax<<<B_, 256>>>(out);
}

// round 5
// speedup vs baseline: 8.9663x; 1.3930x over previous
#include <cuda_runtime.h>
#include <cuda_bf16.h>
#include <cstdint>
#include <math.h>

#define B_    1024
#define D_    1024
#define H_    16
#define S_    50
#define P_    49
#define OUT_  1000
#define EPS_  1e-5f
#define KP_   3072          // bf16x3 expanded K
#define NCH_  96            // KP_/32

// ---------------- scratch / tables (device globals) -------------------------
__device__ float g_pe[S_*D_];
__device__ float g_pemean[S_], g_pe2[S_];
__device__ float g_gvec[S_*16];
__device__ float g_csum[16];
__device__ float g_G[16*16];
__device__ float g_tok0c[D_];
__device__ float g_n0[D_];           // LN1(cls+pe0)
__device__ float g_q0[D_], g_v0[D_];
__device__ float g_score0[H_];
__device__ float g_qk[D_];
__device__ float g_sk[H_*16], g_spk[H_*S_], g_scw[H_], g_scb[H_];
__device__ float g_Mv[16*D_];
__device__ float g_pv[S_*D_];
__device__ float g_cvw[D_], g_cvb[D_];
__device__ float g_tok0[(size_t)B_*D_];
__device__ float g_logits[(size_t)B_*OUT_];
__device__ __nv_bfloat16 g_Zp[(size_t)B_*KP_];          // Z'  [hi|hi|lo]
__device__ __nv_bfloat16 g_Yp[(size_t)B_*KP_];          // Y'  [hi|hi|lo]
__device__ __nv_bfloat16 g_Wmp[(size_t)1024*KP_];       // Wm' [hi|lo|hi]
__device__ __nv_bfloat16 g_Whp[(size_t)1024*KP_];       // Wh' [hi|lo|hi]

// ---------------- PTX helpers ------------------------------------------------
__device__ __forceinline__ uint32_t smem_to_u32(const void* p) {
    uint32_t a;
    asm("{ .reg .u64 tmp; cvta.to.shared.u64 tmp, %1; cvt.u32.u64 %0, tmp; }" : "=r"(a) : "l"(p));
    return a;
}
#define LDMATRIX_X4(r0, r1, r2, r3, addr) \
    asm volatile("ldmatrix.sync.aligned.m8n8.x4.shared.b16 {%0,%1,%2,%3}, [%4];" \
        : "=r"(r0), "=r"(r1), "=r"(r2), "=r"(r3) : "r"(addr))
#define MMA_BF16(d, a, b) \
    asm volatile("mma.sync.aligned.m16n8k16.row.col.f32.bf16.bf16.f32 " \
        "{%0,%1,%2,%3}, {%4,%5,%6,%7}, {%8,%9}, {%0,%1,%2,%3};" \
        : "+f"((d)[0]), "+f"((d)[1]), "+f"((d)[2]), "+f"((d)[3]) \
        : "r"((a)[0]), "r"((a)[1]), "r"((a)[2]), "r"((a)[3]), "r"((b)[0]), "r"((b)[1]))

// ---------------- math helpers ------------------------------------------------
__device__ __forceinline__ float pos_emb(int pos, int d) {
    float fd    = (float)(d & ~1);
    float denom = powf(10000.0f, fd * (1.0f / 1024.0f));
    float ang   = (float)pos / denom;
    return (d & 1) ? cosf(ang) : sinf(ang);
}
__device__ __forceinline__ float block_reduce_sum(float v, float* red) {
    int t = threadIdx.x;
    #pragma unroll
    for (int o = 16; o > 0; o >>= 1) v += __shfl_down_sync(0xffffffffu, v, o);
    if ((t & 31) == 0) red[t >> 5] = v;
    __syncthreads();
    if (t == 0) {
        float s = 0.f; int nw = blockDim.x >> 5;
        for (int i = 0; i < nw; i++) s += red[i];
        red[0] = s;
    }
    __syncthreads();
    float r = red[0];
    __syncthreads();
    return r;
}
__device__ __forceinline__ float block_reduce_max(float v, float* red) {
    int t = threadIdx.x;
    #pragma unroll
    for (int o = 16; o > 0; o >>= 1) v = fmaxf(v, __shfl_down_sync(0xffffffffu, v, o));
    if ((t & 31) == 0) red[t >> 5] = v;
    __syncthreads();
    if (t == 0) {
        float m = red[0]; int nw = blockDim.x >> 5;
        for (int i = 1; i < nw; i++) m = fmaxf(m, red[i]);
        red[0] = m;
    }
    __syncthreads();
    float r = red[0];
    __syncthreads();
    return r;
}
__device__ __forceinline__ void split_bf16(float x, __nv_bfloat16& hi, __nv_bfloat16& lo) {
    hi = __float2bfloat16(x);
    lo = __float2bfloat16(x - __bfloat162float(hi));
}

// ---------------- conv_w: fp32 weight -> bf16x3 B-layout [hi|lo|hi] -----------
__global__ __launch_bounds__(256) void conv_w(const float* __restrict__ W, int rows, int which) {
    size_t i = (size_t)blockIdx.x * 256 + threadIdx.x;
    int r = (int)(i >> 10), k = (int)(i & 1023);
    float v = (r < rows) ? W[(size_t)r * 1024 + k] : 0.f;
    __nv_bfloat16 hi, lo; split_bf16(v, hi, lo);
    __nv_bfloat16* dst = which ? g_Whp : g_Wmp;
    dst[(size_t)r * KP_ + k]        = hi;
    dst[(size_t)r * KP_ + 1024 + k] = lo;
    dst[(size_t)r * KP_ + 2048 + k] = hi;
}

// ---------------- K0a: pe table + per-pos stats + gvec (+stats block) ---------
__global__ __launch_bounds__(256) void k0_pe(const float* __restrict__ Wp) {
    __shared__ float pes[D_];
    __shared__ float red[32];
    __shared__ float partial[16][17];
    __shared__ float chunk[256][17];
    int t = threadIdx.x;

    if (blockIdx.x == 50) {   // Wp^T Wp /1024 + colsums
        int si = t >> 4, tj = t & 15;
        float acc = 0.f, accC = 0.f;
        for (int c = 0; c < 4; c++) {
            for (int idx = t; idx < 4096; idx += 256)
                chunk[idx >> 4][idx & 15] = Wp[(c * 256 + (idx >> 4)) * 16 + (idx & 15)];
            __syncthreads();
            for (int d = 0; d < 256; d++) acc += chunk[d][si] * chunk[d][tj];
            if (t < 16) for (int d = 0; d < 256; d++) accC += chunk[d][t];
            __syncthreads();
        }
        g_G[si * 16 + tj] = acc * (1.0f / D_);
        if (t < 16) g_csum[t] = accC * (1.0f / D_);
        return;
    }

    int pos = blockIdx.x;
    for (int d = t; d < D_; d += 256) {
        float v = pos_emb(pos, d);
        pes[d] = v;
        g_pe[pos * D_ + d] = v;
    }
    __syncthreads();
    float s = 0.f, s2 = 0.f;
    for (int d = t; d < D_; d += 256) { float v = pes[d]; s += v; s2 += v * v; }
    float mean = block_reduce_sum(s, red) * (1.0f / D_);
    float m2   = block_reduce_sum(s2, red) * (1.0f / D_);
    if (t == 0) { g_pemean[pos] = mean; g_pe2[pos] = m2; }

    int sidx = t & 15, grp = t >> 4;
    float acc = 0.f;
    for (int d = grp; d < D_; d += 16) acc += Wp[d * 16 + sidx] * pes[d];
    partial[grp][sidx] = acc;
    __syncthreads();
    if (t < 16) {
        float a = 0.f;
        for (int g = 0; g < 16; g++) a += partial[g][t];
        g_gvec[pos * 16 + t] = a * (1.0f / D_);
    }
}

// ---------------- K0b: cls-row LN only (1 block) -------------------------------
__global__ __launch_bounds__(256) void k0_ln(
    const float* __restrict__ cls, const float* __restrict__ ln1w, const float* __restrict__ ln1b)
{
    __shared__ float tok[D_];
    __shared__ float red[32];
    int t = threadIdx.x;
    for (int d = t; d < D_; d += 256) tok[d] = cls[d] + g_pe[d];
    __syncthreads();
    float s = 0.f;
    for (int d = t; d < D_; d += 256) s += tok[d];
    float mu = block_reduce_sum(s, red) * (1.0f / D_);
    float vs = 0.f;
    for (int d = t; d < D_; d += 256) { float dv = tok[d] - mu; vs += dv * dv; }
    float var  = block_reduce_sum(vs, red) * (1.0f / D_);
    float rstd = rsqrtf(var + EPS_);
    for (int d = t; d < D_; d += 256) {
        g_tok0c[d] = tok[d];
        g_n0[d]    = (tok[d] - mu) * rstd * ln1w[d] + ln1b[d];
    }
}

// ---------------- K0c: per-head projections (grid = 16, smem-staged) -----------
// dyn smem: Wq[64][65] | Wk[64][65] | Wv[64][65] | n0s[64] | qs[64] | ks[64]
#define PROJ_SMEM ((3 * 64 * 65 + 3 * 64) * 4)
__global__ __launch_bounds__(256) void k0_proj(
    const float* __restrict__ Wq, const float* __restrict__ bq,
    const float* __restrict__ Wk, const float* __restrict__ bk,
    const float* __restrict__ Wv, const float* __restrict__ bv)
{
    extern __shared__ float sm[];
    float* Wqs = sm;                       // [64][65]
    float* Wks = sm + 64 * 65;             // [64][65]
    float* Wvs = sm + 2 * 64 * 65;         // [64][65]
    float* n0s = sm + 3 * 64 * 65;
    float* qs  = n0s + 64;
    float* ks  = qs + 64;

    int h = blockIdx.x;
    int t = threadIdx.x;

    for (int idx = t; idx < 4096; idx += 256) {
        int e = idx >> 6, d = idx & 63;
        Wqs[e * 65 + d] = Wq[(size_t)h * 4096 + idx];
        Wks[e * 65 + d] = Wk[(size_t)h * 4096 + idx];
        Wvs[e * 65 + d] = Wv[(size_t)h * 4096 + idx];
    }
    if (t < 64) n0s[t] = g_n0[h * 64 + t];
    __syncthreads();

    if (t < 64) {               // q
        int e = t;
        float a = 0.f;
        #pragma unroll 16
        for (int d = 0; d < 64; d++) a += n0s[d] * Wqs[e * 65 + d];
        a += bq[h * 64 + e];
        qs[e] = a; g_q0[h * 64 + e] = a;
    } else if (t < 128) {       // k
        int e = t - 64;
        float a = 0.f;
        #pragma unroll 16
        for (int d = 0; d < 64; d++) a += n0s[d] * Wks[e * 65 + d];
        ks[e] = a + bk[h * 64 + e];
    } else if (t < 192) {       // v
        int e = t - 128;
        float a = 0.f;
        #pragma unroll 16
        for (int d = 0; d < 64; d++) a += n0s[d] * Wvs[e * 65 + d];
        g_v0[h * 64 + e] = a + bv[h * 64 + e];
    }
    __syncthreads();

    // score0[h] = 32 * q.k   (two warps reduce)
    if (t < 64) {
        float p = qs[t] * ks[t];
        #pragma unroll
        for (int o = 16; o > 0; o >>= 1) p += __shfl_down_sync(0xffffffffu, p, o);
        if (t == 0)  n0s[0] = p;   // reuse smem slots as scratch (n0s no longer needed by score path)
        if (t == 32) n0s[1] = p;
    }
    __syncthreads();
    if (t == 0) g_score0[h] = 32.0f * (n0s[0] + n0s[1]);

    // qk[h,dp] = sum_e qs[e] * Wk[e][dp]   (column read, conflict-free w/ pad)
    if (t < 64) {
        int dp = t;
        float a = 0.f;
        #pragma unroll 16
        for (int e = 0; e < 64; e++) a += qs[e] * Wks[e * 65 + dp];
        g_qk[h * 64 + dp] = a;
    }
}

// ---------------- K0d: per-head tables, 4-way split per head ------------------
__global__ __launch_bounds__(256) void k0_tabs(
    const float* __restrict__ Wp, const float* __restrict__ ln1w, const float* __restrict__ ln1b,
    const float* __restrict__ Wv, const float* __restrict__ bv,
    const float* __restrict__ bk)
{
    int h = blockIdx.x >> 2, q = blockIdx.x & 3;
    __shared__ float Wvs[64][65];
    __shared__ float wpw[64][17];
    __shared__ float pew[S_][65];
    __shared__ float qkr[64], w1h[64], b1h[64];
    int t = threadIdx.x;

    for (int idx = t; idx < 4096; idx += 256)
        Wvs[idx >> 6][idx & 63] = Wv[(size_t)h * 4096 + idx];
    for (int idx = t; idx < 1024; idx += 256) {
        int dp = idx >> 4, s = idx & 15;
        wpw[dp][s] = Wp[(h * 64 + dp) * 16 + s] * ln1w[h * 64 + dp];
    }
    for (int idx = t; idx < S_ * 64; idx += 256) {
        int pos = idx >> 6, dp = idx & 63;
        pew[pos][dp] = g_pe[pos * D_ + h * 64 + dp] * ln1w[h * 64 + dp];
    }
    if (t < 64) {
        qkr[t] = g_qk[h * 64 + t];
        w1h[t] = ln1w[h * 64 + t];
        b1h[t] = ln1b[h * 64 + t];
    }
    __syncthreads();

    {   // Mv quarter
        int idx = q * 256 + t;
        int e = idx >> 4, s = idx & 15;
        float a = 0.f;
        #pragma unroll 8
        for (int d = 0; d < 64; d++) a += Wvs[e][d] * wpw[d][s];
        g_Mv[s * D_ + h * 64 + e] = a;
    }
    // pv quarter
    for (int idx = q * 800 + t; idx < (q + 1) * 800 && idx < 3200; idx += 256) {
        int e = idx / S_, pos = idx % S_;
        float a = 0.f;
        #pragma unroll 8
        for (int d = 0; d < 64; d++) a += Wvs[e][d] * pew[pos][d];
        g_pv[pos * D_ + h * 64 + e] = a;
    }
    if (q == 0) {
        if (t < 64) {
            float aw = 0.f, ab = 0.f;
            #pragma unroll 8
            for (int d = 0; d < 64; d++) { aw += Wvs[t][d] * w1h[d]; ab += Wvs[t][d] * b1h[d]; }
            g_cvw[h * 64 + t] = aw;
            g_cvb[h * 64 + t] = ab + bv[h * 64 + t];
        }
        if (t >= 64 && t < 80) {
            int s = t - 64;
            float a = 0.f;
            for (int d = 0; d < 64; d++) a += qkr[d] * wpw[d][s];
            g_sk[h * 16 + s] = a;
        }
        if (t >= 128 && t < 128 + S_) {
            int pos = t - 128;
            float a = 0.f;
            for (int d = 0; d < 64; d++) a += qkr[d] * pew[pos][d];
            g_spk[h * S_ + pos] = a;
        }
        if (t == 200) {
            float aw = 0.f, ab = 0.f;
            for (int d = 0; d < 64; d++) { aw += qkr[d] * w1h[d]; ab += qkr[d] * b1h[d]; }
            float qb = 0.f;
            for (int e = 0; e < 64; e++) qb += g_q0[h * 64 + e] * bk[h * 64 + e];
            g_scw[h] = aw;
            g_scb[h] = ab + qb;
        }
    }
}

// ---------------- K_MAIN: per-batch attn + LN2 -> Z' bf16x3 -------------------
__global__ __launch_bounds__(256) void k_main(
    const float* __restrict__ x,
    const float* __restrict__ ln2w, const float* __restrict__ ln2b)
{
    int b = blockIdx.x;
    __shared__ float P16[P_][16];
    __shared__ float mu_s[P_], rs_s[P_];
    __shared__ float sc[H_][52];
    __shared__ float wr[H_][52];
    __shared__ float wp16[H_][16];
    __shared__ float A1[H_], A2[H_], w0[H_];
    __shared__ float tok[D_];
    __shared__ float Gs[256], sks[H_][16], csums[16];
    __shared__ float red[32];
    int t = threadIdx.x;

    for (int idx = t; idx < 784; idx += 256) {
        int R = idx / 28, C = idx % 28;
        P16[(R >> 2) * 7 + (C >> 2)][(R & 3) * 4 + (C & 3)] = x[(size_t)b * 784 + idx];
    }
    if (t < 256) Gs[t] = g_G[t];
    for (int idx = t; idx < 256; idx += 256) sks[idx >> 4][idx & 15] = g_sk[idx];
    if (t < 16) csums[t] = g_csum[t];
    __syncthreads();

    if (t < P_) {
        int p = t, pos = p + 1;
        const float* Pp = P16[p];
        float mu = g_pemean[pos];
        #pragma unroll
        for (int s = 0; s < 16; s++) mu += csums[s] * Pp[s];
        float e2 = g_pe2[pos];
        #pragma unroll
        for (int s = 0; s < 16; s++) {
            float acc = 0.f;
            #pragma unroll
            for (int u = 0; u < 16; u++) acc += Gs[s * 16 + u] * Pp[u];
            e2 += acc * Pp[s];
        }
        #pragma unroll
        for (int s = 0; s < 16; s++) e2 += 2.0f * g_gvec[pos * 16 + s] * Pp[s];
        float var = e2 - mu * mu;
        mu_s[p] = mu;
        rs_s[p] = rsqrtf(var + EPS_);
    }
    __syncthreads();

    for (int idx = t; idx < H_ * P_; idx += 256) {
        int h = idx / P_, p = idx % P_, pos = p + 1;
        const float* Pp = P16[p];
        float a = 0.f;
        #pragma unroll
        for (int s = 0; s < 16; s++) a += sks[h][s] * Pp[s];
        float sco = rs_s[p] * (a + g_spk[h * S_ + pos] - mu_s[p] * g_scw[h]) + g_scb[h];
        sc[h][p + 1] = 32.0f * sco;
    }
    if (t < H_) sc[t][0] = g_score0[t];
    __syncthreads();

    if (t < H_) {
        int h = t;
        float m = sc[h][0];
        for (int s = 1; s < S_; s++) m = fmaxf(m, sc[h][s]);
        float sum = 0.f;
        for (int s = 0; s < S_; s++) { float e = expf(sc[h][s] - m); sc[h][s] = e; sum += e; }
        float inv = 1.f / sum;
        for (int s = 0; s < S_; s++) sc[h][s] *= inv;
        w0[h] = sc[h][0];
        A2[h] = 1.0f - sc[h][0];
    }
    __syncthreads();

    for (int idx = t; idx < H_ * P_; idx += 256) {
        int h = idx / P_, p = idx % P_;
        wr[h][p] = sc[h][p + 1] * rs_s[p];
    }
    __syncthreads();

    if (t < H_) {
        float a = 0.f;
        for (int p = 0; p < P_; p++) a += wr[t][p] * mu_s[p];
        A1[t] = a;
    }
    {
        int h = t >> 4, s = t & 15;
        float a = 0.f;
        for (int p = 0; p < P_; p++) a += wr[h][p] * P16[p][s];
        wp16[h][s] = a;
    }
    __syncthreads();

    for (int o = t; o < D_; o += 256) {
        int h = o >> 6;
        float a = w0[h] * g_v0[o];
        #pragma unroll
        for (int s = 0; s < 16; s++) a += g_Mv[s * D_ + o] * wp16[h][s];
        #pragma unroll 7
        for (int p = 0; p < P_; p++) a += wr[h][p] * g_pv[(p + 1) * D_ + o];
        a += -g_cvw[o] * A1[h] + g_cvb[o] * A2[h];
        float tk = g_tok0c[o] + a;
        tok[o] = tk;
        g_tok0[(size_t)b * D_ + o] = tk;
    }
    __syncthreads();

    float s = 0.f;
    for (int d = t; d < D_; d += 256) s += tok[d];
    float mu = block_reduce_sum(s, red) * (1.0f / D_);
    float vs = 0.f;
    for (int d = t; d < D_; d += 256) { float dv = tok[d] - mu; vs += dv * dv; }
    float var  = block_reduce_sum(vs, red) * (1.0f / D_);
    float rstd = rsqrtf(var + EPS_);
    for (int d = t; d < D_; d += 256) {
        float z = (tok[d] - mu) * rstd * ln2w[d] + ln2b[d];
        __nv_bfloat16 hi, lo; split_bf16(z, hi, lo);
        g_Zp[(size_t)b * KP_ + d]        = hi;
        g_Zp[(size_t)b * KP_ + 1024 + d] = hi;
        g_Zp[(size_t)b * KP_ + 2048 + d] = lo;
    }
}

// ---------------- HMMA bf16 GEMM: C(128x128) = A'(128xKP) . B'(128xKP)^T ------
template<int MODE>
__global__ __launch_bounds__(256) void gemm_tc(const float* __restrict__ bias) {
    __shared__ __nv_bfloat16 As[128][40];
    __shared__ __nv_bfloat16 Bs[128][40];
    int t = threadIdx.x;
    int wid = t >> 5, lane = t & 31;
    int warp_m = wid >> 2, warp_n = wid & 3;
    int m0 = blockIdx.y * 128, n0 = blockIdx.x * 128;

    const __nv_bfloat16* Ag = ((MODE == 0) ? g_Zp : g_Yp) + (size_t)m0 * KP_;
    const __nv_bfloat16* Bg = ((MODE == 0) ? g_Wmp : g_Whp) + (size_t)n0 * KP_;

    float acc[4][4][4];
    #pragma unroll
    for (int i = 0; i < 4; i++)
        #pragma unroll
        for (int j = 0; j < 4; j++)
            #pragma unroll
            for (int e = 0; e < 4; e++) acc[i][j][e] = 0.f;

    uint32_t As_base = smem_to_u32(&As[0][0]);
    uint32_t Bs_base = smem_to_u32(&Bs[0][0]);

    int a_row = warp_m * 64 + (lane & 15);
    int a_col8 = (lane >> 4) * 8;
    int b_quad = lane >> 3;
    int b_tile = b_quad >> 1;
    int b_seg8 = (b_quad & 1) * 8;
    int b_row = warp_n * 32 + (lane & 7);

    for (int ch = 0; ch < NCH_; ch++) {
        int k0 = ch * 32;
        #pragma unroll
        for (int it = 0; it < 2; it++) {
            int idx = t + it * 256;
            int r = idx >> 2, seg = (idx & 3) * 8;
            *(uint4*)&As[r][seg] = *(const uint4*)(Ag + (size_t)r * KP_ + k0 + seg);
            *(uint4*)&Bs[r][seg] = *(const uint4*)(Bg + (size_t)r * KP_ + k0 + seg);
        }
        __syncthreads();
        #pragma unroll
        for (int ks = 0; ks < 2; ks++) {
            uint32_t a[4][4];
            #pragma unroll
            for (int i = 0; i < 4; i++) {
                uint32_t addr = As_base + (uint32_t)(((a_row + i * 16) * 40 + ks * 16 + a_col8) * 2);
                LDMATRIX_X4(a[i][0], a[i][1], a[i][2], a[i][3], addr);
            }
            uint32_t bfr[4][2];
            #pragma unroll
            for (int jp = 0; jp < 2; jp++) {
                uint32_t addr = Bs_base + (uint32_t)(((b_row + (jp * 2 + b_tile) * 8) * 40 + ks * 16 + b_seg8) * 2);
                uint32_t r0, r1, r2, r3;
                LDMATRIX_X4(r0, r1, r2, r3, addr);
                bfr[jp * 2][0] = r0; bfr[jp * 2][1] = r1;
                bfr[jp * 2 + 1][0] = r2; bfr[jp * 2 + 1][1] = r3;
            }
            #pragma unroll
            for (int i = 0; i < 4; i++)
                #pragma unroll
                for (int j = 0; j < 4; j++)
                    MMA_BF16(acc[i][j], a[i], bfr[j]);
        }
        __syncthreads();
    }

    int r4 = lane >> 2, c2 = (lane & 3) * 2;
    #pragma unroll
    for (int i = 0; i < 4; i++) {
        #pragma unroll
        for (int j = 0; j < 4; j++) {
            int n = n0 + warp_n * 32 + j * 8 + c2;
            #pragma unroll
            for (int half = 0; half < 2; half++) {
                int m = m0 + warp_m * 64 + i * 16 + r4 + half * 8;
                float v0 = acc[i][j][half * 2 + 0];
                float v1 = acc[i][j][half * 2 + 1];
                if (MODE == 0) {
                    v0 += bias[n]     + g_tok0[(size_t)m * D_ + n];
                    v1 += bias[n + 1] + g_tok0[(size_t)m * D_ + n + 1];
                    __nv_bfloat16 h0, l0, h1, l1;
                    split_bf16(v0, h0, l0); split_bf16(v1, h1, l1);
                    __nv_bfloat162 hp; hp.x = h0; hp.y = h1;
                    __nv_bfloat162 lp; lp.x = l0; lp.y = l1;
                    *(__nv_bfloat162*)&g_Yp[(size_t)m * KP_ + n]        = hp;
                    *(__nv_bfloat162*)&g_Yp[(size_t)m * KP_ + 1024 + n] = hp;
                    *(__nv_bfloat162*)&g_Yp[(size_t)m * KP_ + 2048 + n] = lp;
                } else {
                    if (n < OUT_)     g_logits[(size_t)m * OUT_ + n]     = v0 + bias[n];
                    if (n + 1 < OUT_) g_logits[(size_t)m * OUT_ + n + 1] = v1 + bias[n + 1];
                }
            }
        }
    }
}

// ---------------- K5: row softmax over 1000 logits -----------------------------
__global__ __launch_bounds__(256) void k5_softmax(float* __restrict__ out) {
    int b = blockIdx.x;
    __shared__ float red[32];
    int t = threadIdx.x;
    const float* lg = g_logits + (size_t)b * OUT_;

    float m = -1e30f;
    for (int o = t; o < OUT_; o += 256) m = fmaxf(m, lg[o]);
    m = block_reduce_max(m, red);

    float s = 0.f;
    for (int o = t; o < OUT_; o += 256) s += expf(lg[o] - m);
    float sum = block_reduce_sum(s, red);
    float inv = 1.f / sum;

    float* ob = out + (size_t)b * OUT_;
    for (int o = t; o < OUT_; o += 256) ob[o] = expf(lg[o] - m) * inv;
}

// ---------------- launch --------------------------------------------------------
extern "C" void kernel_launch(void* const* d_in, const int* in_sizes, int n_in,
                              void* d_out, int out_size) {
    const float* x    = (const float*)d_in[0];
    const float* cls  = (const float*)d_in[1];
    const float* Wp   = (const float*)d_in[2];
    const float* ln1w = (const float*)d_in[3];
    const float* ln1b = (const float*)d_in[4];
    const float* Wq   = (const float*)d_in[5];
    const float* bq   = (const float*)d_in[6];
    const float* Wk   = (const float*)d_in[7];
    const float* bk   = (const float*)d_in[8];
    const float* Wv   = (const float*)d_in[9];
    const float* bv   = (const float*)d_in[10];
    const float* ln2w = (const float*)d_in[11];
    const float* ln2b = (const float*)d_in[12];
    const float* Wm   = (const float*)d_in[13];
    const float* bm   = (const float*)d_in[14];
    const float* Wh   = (const float*)d_in[15];
    const float* bh   = (const float*)d_in[16];
    float* out = (float*)d_out;

    cudaFuncSetAttribute(k0_proj, cudaFuncAttributeMaxDynamicSharedMemorySize, PROJ_SMEM);

    conv_w<<<4096, 256>>>(Wm, 1024, 0);
    conv_w<<<4096, 256>>>(Wh, OUT_, 1);
    k0_pe<<<51, 256>>>(Wp);
    k0_ln<<<1, 256>>>(cls, ln1w, ln1b);
    k0_proj<<<H_, 256, PROJ_SMEM>>>(Wq, bq, Wk, bk, Wv, bv);
    k0_tabs<<<64, 256>>>(Wp, ln1w, ln1b, Wv, bv, bk);

    k_main<<<B_, 256>>>(x, ln2w, ln2b);

    dim3 g(8, 8);
    gemm_tc<0><<<g, 256>>>(bm);
    gemm_tc<1><<<g, 256>>>(bh);

    k5_softmax<<<B_, 256>>>(out);
}

// round 6
// speedup vs baseline: 12.5269x; 1.3971x over previous
#include <cuda_runtime.h>
#include <cuda_bf16.h>
#include <cstdint>
#include <math.h>

#define B_    1024
#define D_    1024
#define H_    16
#define S_    50
#define P_    49
#define OUT_  1000
#define EPS_  1e-5f
#define KP_   3072          // bf16x3 expanded K
#define NCH_  96            // KP_/32

// ---------------- scratch / tables (device globals) -------------------------
__device__ float g_pe[S_*D_];
__device__ float g_pemean[S_], g_pe2[S_];
__device__ float g_gvec[S_*16];
__device__ float g_csum[16];
__device__ float g_G[16*16];
__device__ float g_tok0c[D_];
__device__ float g_q0[D_], g_v0[D_];
__device__ float g_score0[H_];
__device__ float g_qk[D_];
__device__ float g_sk[H_*16], g_spk[H_*S_], g_scw[H_], g_scb[H_];
__device__ float g_Mv[16*D_];
__device__ float g_pv[S_*D_];
__device__ float g_cvw[D_], g_cvb[D_];
__device__ float g_tok0[(size_t)B_*D_];
__device__ float g_logits[(size_t)B_*OUT_];
__device__ __nv_bfloat16 g_Zp[(size_t)B_*KP_];          // Z'  [hi|hi|lo]
__device__ __nv_bfloat16 g_Yp[(size_t)B_*KP_];          // Y'  [hi|hi|lo]
__device__ __nv_bfloat16 g_Wmp[(size_t)1024*KP_];       // Wm' [hi|lo|hi]
__device__ __nv_bfloat16 g_Whp[(size_t)1024*KP_];       // Wh' [hi|lo|hi]

// ---------------- PTX helpers ------------------------------------------------
__device__ __forceinline__ uint32_t smem_to_u32(const void* p) {
    uint32_t a;
    asm("{ .reg .u64 tmp; cvta.to.shared.u64 tmp, %1; cvt.u32.u64 %0, tmp; }" : "=r"(a) : "l"(p));
    return a;
}
#define LDMATRIX_X4(r0, r1, r2, r3, addr) \
    asm volatile("ldmatrix.sync.aligned.m8n8.x4.shared.b16 {%0,%1,%2,%3}, [%4];" \
        : "=r"(r0), "=r"(r1), "=r"(r2), "=r"(r3) : "r"(addr))
#define MMA_BF16(d, a, b) \
    asm volatile("mma.sync.aligned.m16n8k16.row.col.f32.bf16.bf16.f32 " \
        "{%0,%1,%2,%3}, {%4,%5,%6,%7}, {%8,%9}, {%0,%1,%2,%3};" \
        : "+f"((d)[0]), "+f"((d)[1]), "+f"((d)[2]), "+f"((d)[3]) \
        : "r"((a)[0]), "r"((a)[1]), "r"((a)[2]), "r"((a)[3]), "r"((b)[0]), "r"((b)[1]))

// ---------------- math helpers ------------------------------------------------
__device__ __forceinline__ float pos_emb(int pos, int d) {
    float fd    = (float)(d & ~1);
    float denom = powf(10000.0f, fd * (1.0f / 1024.0f));
    float ang   = (float)pos / denom;
    return (d & 1) ? cosf(ang) : sinf(ang);
}
__device__ __forceinline__ float block_reduce_sum(float v, float* red) {
    int t = threadIdx.x;
    #pragma unroll
    for (int o = 16; o > 0; o >>= 1) v += __shfl_down_sync(0xffffffffu, v, o);
    if ((t & 31) == 0) red[t >> 5] = v;
    __syncthreads();
    if (t == 0) {
        float s = 0.f; int nw = blockDim.x >> 5;
        for (int i = 0; i < nw; i++) s += red[i];
        red[0] = s;
    }
    __syncthreads();
    float r = red[0];
    __syncthreads();
    return r;
}
__device__ __forceinline__ float block_reduce_max(float v, float* red) {
    int t = threadIdx.x;
    #pragma unroll
    for (int o = 16; o > 0; o >>= 1) v = fmaxf(v, __shfl_down_sync(0xffffffffu, v, o));
    if ((t & 31) == 0) red[t >> 5] = v;
    __syncthreads();
    if (t == 0) {
        float m = red[0]; int nw = blockDim.x >> 5;
        for (int i = 1; i < nw; i++) m = fmaxf(m, red[i]);
        red[0] = m;
    }
    __syncthreads();
    float r = red[0];
    __syncthreads();
    return r;
}
__device__ __forceinline__ void split_bf16(float x, __nv_bfloat16& hi, __nv_bfloat16& lo) {
    hi = __float2bfloat16(x);
    lo = __float2bfloat16(x - __bfloat162float(hi));
}

// ---------------- conv_w2: both weights -> bf16x3 B-layout [hi|lo|hi] ----------
__global__ __launch_bounds__(256) void conv_w2(const float* __restrict__ Wm,
                                               const float* __restrict__ Wh) {
    size_t i = (size_t)blockIdx.x * 256 + threadIdx.x;   // 0 .. 2*2^20-1
    int which = i >= (size_t)(1u << 20);
    int local = (int)(i & ((1u << 20) - 1));
    int r = local >> 10, k = local & 1023;
    const float* W = which ? Wh : Wm;
    int rows = which ? OUT_ : 1024;
    float v = (r < rows) ? W[(size_t)r * 1024 + k] : 0.f;
    __nv_bfloat16 hi, lo; split_bf16(v, hi, lo);
    __nv_bfloat16* dst = which ? g_Whp : g_Wmp;
    dst[(size_t)r * KP_ + k]        = hi;
    dst[(size_t)r * KP_ + 1024 + k] = lo;
    dst[(size_t)r * KP_ + 2048 + k] = hi;
}

// ---------------- K0a: pe table + per-pos stats + gvec (+stats block) ---------
__global__ __launch_bounds__(256) void k0_pe(const float* __restrict__ Wp) {
    __shared__ float pes[D_];
    __shared__ float red[32];
    __shared__ float partial[16][17];
    __shared__ float chunk[256][17];
    int t = threadIdx.x;

    if (blockIdx.x == 50) {   // Wp^T Wp /1024 + colsums
        int si = t >> 4, tj = t & 15;
        float acc = 0.f, accC = 0.f;
        for (int c = 0; c < 4; c++) {
            for (int idx = t; idx < 4096; idx += 256)
                chunk[idx >> 4][idx & 15] = Wp[(c * 256 + (idx >> 4)) * 16 + (idx & 15)];
            __syncthreads();
            for (int d = 0; d < 256; d++) acc += chunk[d][si] * chunk[d][tj];
            if (t < 16) for (int d = 0; d < 256; d++) accC += chunk[d][t];
            __syncthreads();
        }
        g_G[si * 16 + tj] = acc * (1.0f / D_);
        if (t < 16) g_csum[t] = accC * (1.0f / D_);
        return;
    }

    int pos = blockIdx.x;
    for (int d = t; d < D_; d += 256) {
        float v = pos_emb(pos, d);
        pes[d] = v;
        g_pe[pos * D_ + d] = v;
    }
    __syncthreads();
    float s = 0.f, s2 = 0.f;
    for (int d = t; d < D_; d += 256) { float v = pes[d]; s += v; s2 += v * v; }
    float mean = block_reduce_sum(s, red) * (1.0f / D_);
    float m2   = block_reduce_sum(s2, red) * (1.0f / D_);
    if (t == 0) { g_pemean[pos] = mean; g_pe2[pos] = m2; }

    int sidx = t & 15, grp = t >> 4;
    float acc = 0.f;
    for (int d = grp; d < D_; d += 16) acc += Wp[d * 16 + sidx] * pes[d];
    partial[grp][sidx] = acc;
    __syncthreads();
    if (t < 16) {
        float a = 0.f;
        for (int g = 0; g < 16; g++) a += partial[g][t];
        g_gvec[pos * 16 + t] = a * (1.0f / D_);
    }
}

// ---------------- K0c: fused cls-LN + per-head projections (grid = 16) ---------
// dyn smem: Wq[64][65] | Wk[64][65] | Wv[64][65] | n0s[64] | qs[64] | ks[64] | toks[1024] | red[32]
#define PROJ_SMEM ((3 * 64 * 65 + 3 * 64 + 1024 + 32) * 4)
__global__ __launch_bounds__(256) void k0_proj(
    const float* __restrict__ cls, const float* __restrict__ ln1w, const float* __restrict__ ln1b,
    const float* __restrict__ Wq, const float* __restrict__ bq,
    const float* __restrict__ Wk, const float* __restrict__ bk,
    const float* __restrict__ Wv, const float* __restrict__ bv)
{
    extern __shared__ float sm[];
    float* Wqs = sm;
    float* Wks = sm + 64 * 65;
    float* Wvs = sm + 2 * 64 * 65;
    float* n0s = sm + 3 * 64 * 65;
    float* qs  = n0s + 64;
    float* ks  = qs + 64;
    float* toks = ks + 64;
    float* red  = toks + 1024;

    int h = blockIdx.x;
    int t = threadIdx.x;

    for (int idx = t; idx < 4096; idx += 256) {
        int e = idx >> 6, d = idx & 63;
        Wqs[e * 65 + d] = Wq[(size_t)h * 4096 + idx];
        Wks[e * 65 + d] = Wk[(size_t)h * 4096 + idx];
        Wvs[e * 65 + d] = Wv[(size_t)h * 4096 + idx];
    }
    // LN of cls + pe(0): pe(0,d) = (d odd) ? 1 : 0
    float s = 0.f;
    for (int d = t; d < D_; d += 256) {
        float v = cls[d] + (float)(d & 1);
        toks[d] = v; s += v;
    }
    __syncthreads();
    float mu = block_reduce_sum(s, red) * (1.0f / D_);
    float vs = 0.f;
    for (int d = t; d < D_; d += 256) { float dv = toks[d] - mu; vs += dv * dv; }
    float var  = block_reduce_sum(vs, red) * (1.0f / D_);
    float rstd = rsqrtf(var + EPS_);
    if (t < 64) {
        int d = h * 64 + t;
        n0s[t] = (toks[d] - mu) * rstd * ln1w[d] + ln1b[d];
    }
    if (h == 0)
        for (int d = t; d < D_; d += 256) g_tok0c[d] = toks[d];
    __syncthreads();

    if (t < 64) {               // q
        int e = t;
        float a = 0.f;
        #pragma unroll 16
        for (int d = 0; d < 64; d++) a += n0s[d] * Wqs[e * 65 + d];
        a += bq[h * 64 + e];
        qs[e] = a; g_q0[h * 64 + e] = a;
    } else if (t < 128) {       // k
        int e = t - 64;
        float a = 0.f;
        #pragma unroll 16
        for (int d = 0; d < 64; d++) a += n0s[d] * Wks[e * 65 + d];
        ks[e] = a + bk[h * 64 + e];
    } else if (t < 192) {       // v
        int e = t - 128;
        float a = 0.f;
        #pragma unroll 16
        for (int d = 0; d < 64; d++) a += n0s[d] * Wvs[e * 65 + d];
        g_v0[h * 64 + e] = a + bv[h * 64 + e];
    }
    __syncthreads();

    if (t < 64) {   // score0
        float p = qs[t] * ks[t];
        #pragma unroll
        for (int o = 16; o > 0; o >>= 1) p += __shfl_down_sync(0xffffffffu, p, o);
        if (t == 0)  red[0] = p;
        if (t == 32) red[1] = p;
    }
    __syncthreads();
    if (t == 0) g_score0[h] = 32.0f * (red[0] + red[1]);

    if (t < 64) {   // qk
        int dp = t;
        float a = 0.f;
        #pragma unroll 16
        for (int e = 0; e < 64; e++) a += qs[e] * Wks[e * 65 + dp];
        g_qk[h * 64 + dp] = a;
    }
}

// ---------------- K0d: per-head tables, 4-way split per head ------------------
__global__ __launch_bounds__(256) void k0_tabs(
    const float* __restrict__ Wp, const float* __restrict__ ln1w, const float* __restrict__ ln1b,
    const float* __restrict__ Wv, const float* __restrict__ bv,
    const float* __restrict__ bk)
{
    int h = blockIdx.x >> 2, q = blockIdx.x & 3;
    __shared__ float Wvs[64][65];
    __shared__ float wpw[64][17];
    __shared__ float pew[S_][65];
    __shared__ float qkr[64], w1h[64], b1h[64];
    int t = threadIdx.x;

    for (int idx = t; idx < 4096; idx += 256)
        Wvs[idx >> 6][idx & 63] = Wv[(size_t)h * 4096 + idx];
    for (int idx = t; idx < 1024; idx += 256) {
        int dp = idx >> 4, s = idx & 15;
        wpw[dp][s] = Wp[(h * 64 + dp) * 16 + s] * ln1w[h * 64 + dp];
    }
    for (int idx = t; idx < S_ * 64; idx += 256) {
        int pos = idx >> 6, dp = idx & 63;
        pew[pos][dp] = g_pe[pos * D_ + h * 64 + dp] * ln1w[h * 64 + dp];
    }
    if (t < 64) {
        qkr[t] = g_qk[h * 64 + t];
        w1h[t] = ln1w[h * 64 + t];
        b1h[t] = ln1b[h * 64 + t];
    }
    __syncthreads();

    {   // Mv quarter
        int idx = q * 256 + t;
        int e = idx >> 4, s = idx & 15;
        float a = 0.f;
        #pragma unroll 8
        for (int d = 0; d < 64; d++) a += Wvs[e][d] * wpw[d][s];
        g_Mv[s * D_ + h * 64 + e] = a;
    }
    // pv quarter
    for (int idx = q * 800 + t; idx < (q + 1) * 800 && idx < 3200; idx += 256) {
        int e = idx / S_, pos = idx % S_;
        float a = 0.f;
        #pragma unroll 8
        for (int d = 0; d < 64; d++) a += Wvs[e][d] * pew[pos][d];
        g_pv[pos * D_ + h * 64 + e] = a;
    }
    if (q == 0) {
        if (t < 64) {
            float aw = 0.f, ab = 0.f;
            #pragma unroll 8
            for (int d = 0; d < 64; d++) { aw += Wvs[t][d] * w1h[d]; ab += Wvs[t][d] * b1h[d]; }
            g_cvw[h * 64 + t] = aw;
            g_cvb[h * 64 + t] = ab + bv[h * 64 + t];
        }
        if (t >= 64 && t < 80) {
            int s = t - 64;
            float a = 0.f;
            for (int d = 0; d < 64; d++) a += qkr[d] * wpw[d][s];
            g_sk[h * 16 + s] = a;
        }
        if (t >= 128 && t < 128 + S_) {
            int pos = t - 128;
            float a = 0.f;
            for (int d = 0; d < 64; d++) a += qkr[d] * pew[pos][d];
            g_spk[h * S_ + pos] = a;
        }
        if (t == 200) {
            float aw = 0.f, ab = 0.f;
            for (int d = 0; d < 64; d++) { aw += qkr[d] * w1h[d]; ab += qkr[d] * b1h[d]; }
            float qb = 0.f;
            for (int e = 0; e < 64; e++) qb += g_q0[h * 64 + e] * bk[h * 64 + e];
            g_scw[h] = aw;
            g_scb[h] = ab + qb;
        }
    }
}

// ---------------- K_MAIN: 2 batches per block ----------------------------------
__global__ __launch_bounds__(256) void k_main(
    const float* __restrict__ x,
    const float* __restrict__ ln2w, const float* __restrict__ ln2b)
{
    int b0 = blockIdx.x * 2;
    __shared__ float  P16[2][P_][16];
    __shared__ float  mu_s[2][P_], rs_s[2][P_];
    __shared__ float  sc[2][H_][52];
    __shared__ float2 wr2[H_][52];      // (b0, b1) pairs
    __shared__ float2 wp2[H_][16];
    __shared__ float2 w0a[H_], A1s[H_], A2s[H_];
    __shared__ float  tok[2][D_];
    __shared__ float  Gs[256], sks[H_][16], csums[16];
    __shared__ float  red[32];
    int t = threadIdx.x;

    for (int idx = t; idx < 2 * 784; idx += 256) {
        int bb = idx >= 784, i = idx - bb * 784;
        int R = i / 28, C = i % 28;
        P16[bb][(R >> 2) * 7 + (C >> 2)][(R & 3) * 4 + (C & 3)] = x[(size_t)(b0 + bb) * 784 + i];
    }
    if (t < 256) Gs[t] = g_G[t];
    for (int idx = t; idx < 256; idx += 256) sks[idx >> 4][idx & 15] = g_sk[idx];
    if (t < 16) csums[t] = g_csum[t];
    __syncthreads();

    if (t < 2 * P_) {
        int bb = t / P_, p = t - bb * P_, pos = p + 1;
        const float* Pp = P16[bb][p];
        float mu = g_pemean[pos];
        #pragma unroll
        for (int s = 0; s < 16; s++) mu += csums[s] * Pp[s];
        float e2 = g_pe2[pos];
        #pragma unroll
        for (int s = 0; s < 16; s++) {
            float acc = 0.f;
            #pragma unroll
            for (int u = 0; u < 16; u++) acc += Gs[s * 16 + u] * Pp[u];
            e2 += acc * Pp[s];
        }
        #pragma unroll
        for (int s = 0; s < 16; s++) e2 += 2.0f * g_gvec[pos * 16 + s] * Pp[s];
        float var = e2 - mu * mu;
        mu_s[bb][p] = mu;
        rs_s[bb][p] = rsqrtf(var + EPS_);
    }
    __syncthreads();

    for (int idx = t; idx < 2 * H_ * P_; idx += 256) {
        int bb = idx / (H_ * P_);
        int r = idx - bb * H_ * P_;
        int h = r / P_, p = r - h * P_, pos = p + 1;
        const float* Pp = P16[bb][p];
        float a = 0.f;
        #pragma unroll
        for (int s = 0; s < 16; s++) a += sks[h][s] * Pp[s];
        float sco = rs_s[bb][p] * (a + g_spk[h * S_ + pos] - mu_s[bb][p] * g_scw[h]) + g_scb[h];
        sc[bb][h][p + 1] = 32.0f * sco;
    }
    if (t < 32) sc[t >> 4][t & 15][0] = g_score0[t & 15];
    __syncthreads();

    if (t < 32) {
        int bb = t >> 4, h = t & 15;
        float m = sc[bb][h][0];
        for (int s = 1; s < S_; s++) m = fmaxf(m, sc[bb][h][s]);
        float sum = 0.f;
        for (int s = 0; s < S_; s++) { float e = expf(sc[bb][h][s] - m); sc[bb][h][s] = e; sum += e; }
        float inv = 1.f / sum;
        for (int s = 0; s < S_; s++) sc[bb][h][s] *= inv;
        float w0 = sc[bb][h][0];
        ((float*)&w0a[h])[bb] = w0;
        ((float*)&A2s[h])[bb] = 1.0f - w0;
    }
    __syncthreads();

    for (int idx = t; idx < 2 * H_ * P_; idx += 256) {
        int bb = idx / (H_ * P_);
        int r = idx - bb * H_ * P_;
        int h = r / P_, p = r - h * P_;
        ((float*)&wr2[h][p])[bb] = sc[bb][h][p + 1] * rs_s[bb][p];
    }
    __syncthreads();

    if (t < 32) {
        int bb = t >> 4, h = t & 15;
        float a = 0.f;
        for (int p = 0; p < P_; p++) a += ((float*)&wr2[h][p])[bb] * mu_s[bb][p];
        ((float*)&A1s[h])[bb] = a;
    }
    for (int idx = t; idx < 2 * H_ * 16; idx += 256) {
        int bb = idx >> 8, h = (idx >> 4) & 15, s = idx & 15;
        float a = 0.f;
        for (int p = 0; p < P_; p++) a += ((float*)&wr2[h][p])[bb] * P16[bb][p][s];
        ((float*)&wp2[h][s])[bb] = a;
    }
    __syncthreads();

    // attn + residual (shared pv/Mv loads across both batches)
    for (int o = t; o < D_; o += 256) {
        int h = o >> 6;
        float v0v = g_v0[o];
        float2 w0v = w0a[h];
        float a0 = w0v.x * v0v, a1 = w0v.y * v0v;
        #pragma unroll
        for (int s = 0; s < 16; s++) {
            float m = g_Mv[s * D_ + o];
            float2 wp = wp2[h][s];
            a0 += m * wp.x; a1 += m * wp.y;
        }
        #pragma unroll 7
        for (int p = 0; p < P_; p++) {
            float pv = g_pv[(p + 1) * D_ + o];
            float2 w = wr2[h][p];
            a0 += w.x * pv; a1 += w.y * pv;
        }
        float cvw = g_cvw[o], cvb = g_cvb[o], tc = g_tok0c[o];
        float2 a1v = A1s[h], a2v = A2s[h];
        float tk0 = tc + a0 - cvw * a1v.x + cvb * a2v.x;
        float tk1 = tc + a1 - cvw * a1v.y + cvb * a2v.y;
        tok[0][o] = tk0; tok[1][o] = tk1;
        g_tok0[(size_t)b0 * D_ + o]       = tk0;
        g_tok0[(size_t)(b0 + 1) * D_ + o] = tk1;
    }
    __syncthreads();

    // LN2 per batch
    for (int bb = 0; bb < 2; bb++) {
        float s = 0.f;
        for (int d = t; d < D_; d += 256) s += tok[bb][d];
        float mu = block_reduce_sum(s, red) * (1.0f / D_);
        float vs = 0.f;
        for (int d = t; d < D_; d += 256) { float dv = tok[bb][d] - mu; vs += dv * dv; }
        float var  = block_reduce_sum(vs, red) * (1.0f / D_);
        float rstd = rsqrtf(var + EPS_);
        size_t base = (size_t)(b0 + bb) * KP_;
        for (int d = t; d < D_; d += 256) {
            float z = (tok[bb][d] - mu) * rstd * ln2w[d] + ln2b[d];
            __nv_bfloat16 hi, lo; split_bf16(z, hi, lo);
            g_Zp[base + d]        = hi;
            g_Zp[base + 1024 + d] = hi;
            g_Zp[base + 2048 + d] = lo;
        }
    }
}

// ---------------- HMMA bf16 GEMM: 64x128 CTA tile, register prefetch -----------
// 8 warps: warp_m = wid>>2 (32 rows), warp_n = wid&3 (32 cols); 2x4 m16n8 tiles.
template<int MODE>
__global__ __launch_bounds__(256) void gemm_tc(const float* __restrict__ bias) {
    __shared__ __nv_bfloat16 As[64][40];
    __shared__ __nv_bfloat16 Bs[128][40];
    int t = threadIdx.x;
    int wid = t >> 5, lane = t & 31;
    int warp_m = wid >> 2, warp_n = wid & 3;
    int m0 = blockIdx.y * 64, n0 = blockIdx.x * 128;

    const __nv_bfloat16* Ag = ((MODE == 0) ? g_Zp : g_Yp) + (size_t)m0 * KP_;
    const __nv_bfloat16* Bg = ((MODE == 0) ? g_Wmp : g_Whp) + (size_t)n0 * KP_;

    float acc[2][4][4];
    #pragma unroll
    for (int i = 0; i < 2; i++)
        #pragma unroll
        for (int j = 0; j < 4; j++)
            #pragma unroll
            for (int e = 0; e < 4; e++) acc[i][j][e] = 0.f;

    uint32_t As_base = smem_to_u32(&As[0][0]);
    uint32_t Bs_base = smem_to_u32(&Bs[0][0]);

    int ar = t >> 2, aseg = (t & 3) * 8;     // A: 64 rows x 32k = 256 uint4
    // B: 128 rows x 32k = 512 uint4: rows ar and ar+64

    int a_row = warp_m * 32 + (lane & 15);
    int a_col8 = (lane >> 4) * 8;
    int b_quad = lane >> 3;
    int b_tile = b_quad >> 1;
    int b_seg8 = (b_quad & 1) * 8;
    int b_row = warp_n * 32 + (lane & 7);

    // prefetch chunk 0
    uint4 ra  = *(const uint4*)(Ag + (size_t)ar * KP_ + aseg);
    uint4 rb0 = *(const uint4*)(Bg + (size_t)ar * KP_ + aseg);
    uint4 rb1 = *(const uint4*)(Bg + (size_t)(ar + 64) * KP_ + aseg);

    for (int ch = 0; ch < NCH_; ch++) {
        *(uint4*)&As[ar][aseg]      = ra;
        *(uint4*)&Bs[ar][aseg]      = rb0;
        *(uint4*)&Bs[ar + 64][aseg] = rb1;
        __syncthreads();
        if (ch + 1 < NCH_) {
            int k0 = (ch + 1) * 32;
            ra  = *(const uint4*)(Ag + (size_t)ar * KP_ + k0 + aseg);
            rb0 = *(const uint4*)(Bg + (size_t)ar * KP_ + k0 + aseg);
            rb1 = *(const uint4*)(Bg + (size_t)(ar + 64) * KP_ + k0 + aseg);
        }
        #pragma unroll
        for (int ks = 0; ks < 2; ks++) {
            uint32_t a[2][4];
            #pragma unroll
            for (int i = 0; i < 2; i++) {
                uint32_t addr = As_base + (uint32_t)(((a_row + i * 16) * 40 + ks * 16 + a_col8) * 2);
                LDMATRIX_X4(a[i][0], a[i][1], a[i][2], a[i][3], addr);
            }
            uint32_t bfr[4][2];
            #pragma unroll
            for (int jp = 0; jp < 2; jp++) {
                uint32_t addr = Bs_base + (uint32_t)(((b_row + (jp * 2 + b_tile) * 8) * 40 + ks * 16 + b_seg8) * 2);
                uint32_t r0, r1, r2, r3;
                LDMATRIX_X4(r0, r1, r2, r3, addr);
                bfr[jp * 2][0] = r0; bfr[jp * 2][1] = r1;
                bfr[jp * 2 + 1][0] = r2; bfr[jp * 2 + 1][1] = r3;
            }
            #pragma unroll
            for (int i = 0; i < 2; i++)
                #pragma unroll
                for (int j = 0; j < 4; j++)
                    MMA_BF16(acc[i][j], a[i], bfr[j]);
        }
        __syncthreads();
    }

    int r4 = lane >> 2, c2 = (lane & 3) * 2;
    #pragma unroll
    for (int i = 0; i < 2; i++) {
        #pragma unroll
        for (int j = 0; j < 4; j++) {
            int n = n0 + warp_n * 32 + j * 8 + c2;
            #pragma unroll
            for (int half = 0; half < 2; half++) {
                int m = m0 + warp_m * 32 + i * 16 + r4 + half * 8;
                float v0 = acc[i][j][half * 2 + 0];
                float v1 = acc[i][j][half * 2 + 1];
                if (MODE == 0) {
                    v0 += bias[n]     + g_tok0[(size_t)m * D_ + n];
                    v1 += bias[n + 1] + g_tok0[(size_t)m * D_ + n + 1];
                    __nv_bfloat16 h0, l0, h1, l1;
                    split_bf16(v0, h0, l0); split_bf16(v1, h1, l1);
                    __nv_bfloat162 hp; hp.x = h0; hp.y = h1;
                    __nv_bfloat162 lp; lp.x = l0; lp.y = l1;
                    *(__nv_bfloat162*)&g_Yp[(size_t)m * KP_ + n]        = hp;
                    *(__nv_bfloat162*)&g_Yp[(size_t)m * KP_ + 1024 + n] = hp;
                    *(__nv_bfloat162*)&g_Yp[(size_t)m * KP_ + 2048 + n] = lp;
                } else {
                    if (n < OUT_)     g_logits[(size_t)m * OUT_ + n]     = v0 + bias[n];
                    if (n + 1 < OUT_) g_logits[(size_t)m * OUT_ + n + 1] = v1 + bias[n + 1];
                }
            }
        }
    }
}

// ---------------- K5: row softmax over 1000 logits -----------------------------
__global__ __launch_bounds__(256) void k5_softmax(float* __restrict__ out) {
    int b = blockIdx.x;
    __shared__ float red[32];
    int t = threadIdx.x;
    const float* lg = g_logits + (size_t)b * OUT_;

    float m = -1e30f;
    for (int o = t; o < OUT_; o += 256) m = fmaxf(m, lg[o]);
    m = block_reduce_max(m, red);

    float s = 0.f;
    for (int o = t; o < OUT_; o += 256) s += expf(lg[o] - m);
    float sum = block_reduce_sum(s, red);
    float inv = 1.f / sum;

    float* ob = out + (size_t)b * OUT_;
    for (int o = t; o < OUT_; o += 256) ob[o] = expf(lg[o] - m) * inv;
}

// ---------------- launch --------------------------------------------------------
extern "C" void kernel_launch(void* const* d_in, const int* in_sizes, int n_in,
                              void* d_out, int out_size) {
    const float* x    = (const float*)d_in[0];
    const float* cls  = (const float*)d_in[1];
    const float* Wp   = (const float*)d_in[2];
    const float* ln1w = (const float*)d_in[3];
    const float* ln1b = (const float*)d_in[4];
    const float* Wq   = (const float*)d_in[5];
    const float* bq   = (const float*)d_in[6];
    const float* Wk   = (const float*)d_in[7];
    const float* bk   = (const float*)d_in[8];
    const float* Wv   = (const float*)d_in[9];
    const float* bv   = (const float*)d_in[10];
    const float* ln2w = (const float*)d_in[11];
    const float* ln2b = (const float*)d_in[12];
    const float* Wm   = (const float*)d_in[13];
    const float* bm   = (const float*)d_in[14];
    const float* Wh   = (const float*)d_in[15];
    const float* bh   = (const float*)d_in[16];
    float* out = (float*)d_out;

    cudaFuncSetAttribute(k0_proj, cudaFuncAttributeMaxDynamicSharedMemorySize, PROJ_SMEM);

    conv_w2<<<8192, 256>>>(Wm, Wh);
    k0_pe<<<51, 256>>>(Wp);
    k0_proj<<<H_, 256, PROJ_SMEM>>>(cls, ln1w, ln1b, Wq, bq, Wk, bk, Wv, bv);
    k0_tabs<<<64, 256>>>(Wp, ln1w, ln1b, Wv, bv, bk);

    k_main<<<B_ / 2, 256>>>(x, ln2w, ln2b);

    dim3 g(8, 16);
    gemm_tc<0><<<g, 256>>>(bm);
    gemm_tc<1><<<g, 256>>>(bh);

    k5_softmax<<<B_, 256>>>(out);
}

// round 9
// speedup vs baseline: 13.7214x; 1.0954x over previous
#include <cuda_runtime.h>
#include <cuda_bf16.h>
#include <cstdint>
#include <math.h>

#define B_    1024
#define D_    1024
#define H_    16
#define S_    50
#define P_    49
#define OUT_  1000
#define EPS_  1e-5f
#define KP_   3072          // bf16x3 expanded K
#define NCH_  96            // KP_/32

// ---------------- scratch / tables (device globals) -------------------------
__device__ float g_pemean[S_], g_pe2[S_];
__device__ float g_gvec[S_*16];
__device__ float g_csum[16];
__device__ float g_G[16*16];
__device__ float g_tok0c[D_];
__device__ float g_v0[D_];
__device__ float g_score0[H_];
__device__ float g_sk[H_*16], g_spk[H_*S_], g_scw[H_], g_scb[H_];
__device__ float g_Mv[16*D_];
__device__ float g_pv[S_*D_];
__device__ float g_cvw[D_], g_cvb[D_];
__device__ float g_tok0[(size_t)B_*D_];
__device__ float g_logits[(size_t)B_*OUT_];
__device__ __nv_bfloat16 g_Zp[(size_t)B_*KP_];          // Z'  [hi|hi|lo]
__device__ __nv_bfloat16 g_Yp[(size_t)B_*KP_];          // Y'  [hi|hi|lo]
__device__ __nv_bfloat16 g_Wmp[(size_t)1024*KP_];       // Wm' [hi|lo|hi]
__device__ __nv_bfloat16 g_Whp[(size_t)1024*KP_];       // Wh' [hi|lo|hi]

// ---------------- PTX helpers ------------------------------------------------
__device__ __forceinline__ uint32_t smem_to_u32(const void* p) {
    uint32_t a;
    asm("{ .reg .u64 tmp; cvta.to.shared.u64 tmp, %1; cvt.u32.u64 %0, tmp; }" : "=r"(a) : "l"(p));
    return a;
}
#define LDMATRIX_X4(r0, r1, r2, r3, addr) \
    asm volatile("ldmatrix.sync.aligned.m8n8.x4.shared.b16 {%0,%1,%2,%3}, [%4];" \
        : "=r"(r0), "=r"(r1), "=r"(r2), "=r"(r3) : "r"(addr))
#define MMA_BF16(d, a, b) \
    asm volatile("mma.sync.aligned.m16n8k16.row.col.f32.bf16.bf16.f32 " \
        "{%0,%1,%2,%3}, {%4,%5,%6,%7}, {%8,%9}, {%0,%1,%2,%3};" \
        : "+f"((d)[0]), "+f"((d)[1]), "+f"((d)[2]), "+f"((d)[3]) \
        : "r"((a)[0]), "r"((a)[1]), "r"((a)[2]), "r"((a)[3]), "r"((b)[0]), "r"((b)[1]))

// ---------------- math helpers ------------------------------------------------
__device__ __forceinline__ float pos_emb(int pos, int d) {
    float fd    = (float)(d & ~1);
    float denom = powf(10000.0f, fd * (1.0f / 1024.0f));
    float ang   = (float)pos / denom;
    return (d & 1) ? cosf(ang) : sinf(ang);
}
__device__ __forceinline__ float block_reduce_sum(float v, float* red) {
    int t = threadIdx.x;
    #pragma unroll
    for (int o = 16; o > 0; o >>= 1) v += __shfl_down_sync(0xffffffffu, v, o);
    if ((t & 31) == 0) red[t >> 5] = v;
    __syncthreads();
    if (t == 0) {
        float s = 0.f; int nw = blockDim.x >> 5;
        for (int i = 0; i < nw; i++) s += red[i];
        red[0] = s;
    }
    __syncthreads();
    float r = red[0];
    __syncthreads();
    return r;
}
__device__ __forceinline__ float block_reduce_max(float v, float* red) {
    int t = threadIdx.x;
    #pragma unroll
    for (int o = 16; o > 0; o >>= 1) v = fmaxf(v, __shfl_down_sync(0xffffffffu, v, o));
    if ((t & 31) == 0) red[t >> 5] = v;
    __syncthreads();
    if (t == 0) {
        float m = red[0]; int nw = blockDim.x >> 5;
        for (int i = 1; i < nw; i++) m = fmaxf(m, red[i]);
        red[0] = m;
    }
    __syncthreads();
    float r = red[0];
    __syncthreads();
    return r;
}
__device__ __forceinline__ void split_bf16(float x, __nv_bfloat16& hi, __nv_bfloat16& lo) {
    hi = __float2bfloat16(x);
    lo = __float2bfloat16(x - __bfloat162float(hi));
}

// ---------------- K0 MEGA: all precompute in one launch -------------------------
// blocks [0,512):    conv both weight matrices -> bf16x3 [hi|lo|hi]
// blocks [512,562):  pe-pos stats: pemean/pe2/gvec   (pos = bid-512)
// block  562:        Wp^T Wp /1024 (G) + csum        (loads ALL 16384 floats of Wp)
// blocks [563,579):  per-head: cls-LN + q/k/v/score0/qk + all tables (h = bid-563)
#define MEGA_SMEM (18500 * 4)
__global__ __launch_bounds__(1024) void k0_mega(
    const float* __restrict__ cls, const float* __restrict__ ln1w, const float* __restrict__ ln1b,
    const float* __restrict__ Wp,
    const float* __restrict__ Wq, const float* __restrict__ bq,
    const float* __restrict__ Wk, const float* __restrict__ bk,
    const float* __restrict__ Wv, const float* __restrict__ bv,
    const float* __restrict__ Wm, const float* __restrict__ Wh)
{
    extern __shared__ float sm[];
    int bid = blockIdx.x;
    int t = threadIdx.x;

    if (bid < 512) {               // ---- conv role: 4 floats per thread --------
        int idx4 = bid * 1024 + t;              // 0 .. 512K-1
        int which = idx4 >= (1 << 18);
        int l4 = idx4 & ((1 << 18) - 1);
        int r = l4 >> 8;
        int k4 = (l4 & 255) * 4;
        const float* W = which ? Wh : Wm;
        int rows = which ? OUT_ : 1024;
        float4 v = make_float4(0.f, 0.f, 0.f, 0.f);
        if (r < rows) v = *(const float4*)&W[(size_t)r * 1024 + k4];
        __nv_bfloat16 h0, l0, h1, l1, h2, l2, h3, l3;
        split_bf16(v.x, h0, l0); split_bf16(v.y, h1, l1);
        split_bf16(v.z, h2, l2); split_bf16(v.w, h3, l3);
        __nv_bfloat162 hp0, hp1, lp0, lp1;
        hp0.x = h0; hp0.y = h1; hp1.x = h2; hp1.y = h3;
        lp0.x = l0; lp0.y = l1; lp1.x = l2; lp1.y = l3;
        __nv_bfloat16* dst = which ? g_Whp : g_Wmp;
        size_t base = (size_t)r * KP_ + k4;
        // B-operand layout is [hi | lo | hi]  (pairs with A's [hi | hi | lo])
        *(__nv_bfloat162*)&dst[base]            = hp0;
        *(__nv_bfloat162*)&dst[base + 2]        = hp1;
        *(__nv_bfloat162*)&dst[base + 1024]     = lp0;
        *(__nv_bfloat162*)&dst[base + 1026]     = lp1;
        *(__nv_bfloat162*)&dst[base + 2048]     = hp0;
        *(__nv_bfloat162*)&dst[base + 2050]     = hp1;
        return;
    }

    if (bid < 562) {               // ---- pe-pos role -----------------------------
        float* pes     = sm;               // 1024
        float* partial = sm + 1024;        // 64*17
        float* red     = sm + 1024 + 1088; // 32
        int pos = bid - 512;
        float v = pos_emb(pos, t);
        pes[t] = v;
        __syncthreads();
        float mean = block_reduce_sum(v, red) * (1.0f / D_);
        float m2   = block_reduce_sum(v * v, red) * (1.0f / D_);
        if (t == 0) { g_pemean[pos] = mean; g_pe2[pos] = m2; }

        int s = t & 15, grp = t >> 4;      // 64 groups of 16 d's
        float acc = 0.f;
        #pragma unroll
        for (int i = 0; i < 16; i++) {
            int d = grp * 16 + i;
            acc += Wp[d * 16 + s] * pes[d];
        }
        partial[grp * 17 + s] = acc;
        __syncthreads();
        if (t < 16) {
            float a = 0.f;
            for (int g = 0; g < 64; g++) a += partial[g * 17 + t];
            g_gvec[pos * 16 + t] = a * (1.0f / D_);
        }
        return;
    }

    if (bid == 562) {              // ---- Gram role -------------------------------
        float* wps     = sm;               // 16384 = ALL of Wp (1024 rows x 16)
        float* qpart   = sm + 16384;       // 1024
        float* partial = sm + 17408;       // 1088
        for (int idx = t; idx < 16384; idx += 1024) wps[idx] = Wp[idx];
        __syncthreads();
        {
            int p = t & 255, q = t >> 8;
            int si = p >> 4, tj = p & 15;
            float acc = 0.f;
            #pragma unroll 8
            for (int i = 0; i < 256; i++) {
                int d = q * 256 + i;
                acc += wps[d * 16 + si] * wps[d * 16 + tj];
            }
            qpart[q * 256 + p] = acc;
        }
        {
            int s = t & 15, grp = t >> 4;
            float ac = 0.f;
            #pragma unroll
            for (int i = 0; i < 16; i++) ac += wps[(grp * 16 + i) * 16 + s];
            partial[grp * 17 + s] = ac;
        }
        __syncthreads();
        if (t < 256)
            g_G[t] = (qpart[t] + qpart[256 + t] + qpart[512 + t] + qpart[768 + t]) * (1.0f / D_);
        if (t < 16) {
            float a = 0.f;
            for (int g = 0; g < 64; g++) a += partial[g * 17 + t];
            g_csum[t] = a * (1.0f / D_);
        }
        return;
    }

    // ---- head role -------------------------------------------------------------
    int h = bid - 563;
    float* Wqs  = sm;                  // 64*65
    float* Wks  = sm + 4160;
    float* Wvs  = sm + 8320;
    float* wpw  = sm + 12480;          // 64*17
    float* pew  = sm + 13568;          // 50*65
    float* toks = sm + 16818;          // 1024
    float* n0s  = sm + 17842;          // 64
    float* qs   = sm + 17906;          // 64
    float* ks   = sm + 17970;          // 64
    float* qkr  = sm + 18034;          // 64
    float* red  = sm + 18098;          // 32

    for (int idx = t; idx < 4096; idx += 1024) {
        int e = idx >> 6, d = idx & 63;
        Wqs[e * 65 + d] = Wq[(size_t)h * 4096 + idx];
        Wks[e * 65 + d] = Wk[(size_t)h * 4096 + idx];
        Wvs[e * 65 + d] = Wv[(size_t)h * 4096 + idx];
    }
    // cls + pe(0): pe(0,d) = d&1
    float tv = cls[t] + (float)(t & 1);
    toks[t] = tv;
    // wpw
    {
        int dp = t >> 4, s = t & 15;
        wpw[dp * 17 + s] = Wp[(h * 64 + dp) * 16 + s] * ln1w[h * 64 + dp];
    }
    __syncthreads();
    float mu = block_reduce_sum(tv, red) * (1.0f / D_);
    float dv = tv - mu;
    float var  = block_reduce_sum(dv * dv, red) * (1.0f / D_);
    float rstd = rsqrtf(var + EPS_);
    if (t < 64) {
        int d = h * 64 + t;
        n0s[t] = (toks[d] - mu) * rstd * ln1w[d] + ln1b[d];
    }
    if (h == 0) g_tok0c[t] = tv;
    // pew (inline pos-emb)
    for (int idx = t; idx < 3200; idx += 1024) {
        int pos = idx >> 6, dp = idx & 63;
        int d = h * 64 + dp;
        pew[pos * 65 + dp] = pos_emb(pos, d) * ln1w[d];
    }
    __syncthreads();

    if (t < 64) {               // q
        float a = 0.f;
        #pragma unroll 16
        for (int d = 0; d < 64; d++) a += n0s[d] * Wqs[t * 65 + d];
        qs[t] = a + bq[h * 64 + t];
    } else if (t < 128) {       // k
        int e = t - 64;
        float a = 0.f;
        #pragma unroll 16
        for (int d = 0; d < 64; d++) a += n0s[d] * Wks[e * 65 + d];
        ks[e] = a + bk[h * 64 + e];
    } else if (t < 192) {       // v
        int e = t - 128;
        float a = 0.f;
        #pragma unroll 16
        for (int d = 0; d < 64; d++) a += n0s[d] * Wvs[e * 65 + d];
        g_v0[h * 64 + e] = a + bv[h * 64 + e];
    }
    __syncthreads();

    if (t < 64) {               // score0
        float p = qs[t] * ks[t];
        #pragma unroll
        for (int o = 16; o > 0; o >>= 1) p += __shfl_down_sync(0xffffffffu, p, o);
        if (t == 0)  red[0] = p;
        if (t == 32) red[1] = p;
    }
    if (t >= 64 && t < 128) {   // qk
        int dp = t - 64;
        float a = 0.f;
        #pragma unroll 16
        for (int e = 0; e < 64; e++) a += qs[e] * Wks[e * 65 + dp];
        qkr[dp] = a;
    }
    __syncthreads();
    if (t == 0) g_score0[h] = 32.0f * (red[0] + red[1]);

    // Mv: one output per thread
    {
        int e = t >> 4, s = t & 15;
        float a = 0.f;
        #pragma unroll 16
        for (int d = 0; d < 64; d++) a += Wvs[e * 65 + d] * wpw[d * 17 + s];
        g_Mv[s * D_ + h * 64 + e] = a;
    }
    // pv
    for (int idx = t; idx < 3200; idx += 1024) {
        int e = idx / S_, pos = idx % S_;
        float a = 0.f;
        #pragma unroll 16
        for (int d = 0; d < 64; d++) a += Wvs[e * 65 + d] * pew[pos * 65 + d];
        g_pv[pos * D_ + h * 64 + e] = a;
    }
    // scalars
    if (t < 64) {
        float aw = 0.f, ab = 0.f;
        #pragma unroll 16
        for (int d = 0; d < 64; d++) {
            float wvd = Wvs[t * 65 + d];
            aw += wvd * ln1w[h * 64 + d];
            ab += wvd * ln1b[h * 64 + d];
        }
        g_cvw[h * 64 + t] = aw;
        g_cvb[h * 64 + t] = ab + bv[h * 64 + t];
    }
    if (t >= 64 && t < 80) {
        int s = t - 64;
        float a = 0.f;
        for (int d = 0; d < 64; d++) a += qkr[d] * wpw[d * 17 + s];
        g_sk[h * 16 + s] = a;
    }
    if (t >= 128 && t < 128 + S_) {
        int pos = t - 128;
        float a = 0.f;
        for (int d = 0; d < 64; d++) a += qkr[d] * pew[pos * 65 + d];
        g_spk[h * S_ + pos] = a;
    }
    if (t == 200) {
        float aw = 0.f, ab = 0.f;
        for (int d = 0; d < 64; d++) {
            aw += qkr[d] * ln1w[h * 64 + d];
            ab += qkr[d] * ln1b[h * 64 + d];
        }
        float qb = 0.f;
        for (int e = 0; e < 64; e++) qb += qs[e] * bk[h * 64 + e];
        g_scw[h] = aw;
        g_scb[h] = ab + qb;
    }
}

// ---------------- K_MAIN: 2 batches per block ----------------------------------
__global__ __launch_bounds__(256) void k_main(
    const float* __restrict__ x,
    const float* __restrict__ ln2w, const float* __restrict__ ln2b)
{
    int b0 = blockIdx.x * 2;
    __shared__ float  P16[2][P_][16];
    __shared__ float  mu_s[2][P_], rs_s[2][P_];
    __shared__ float  sc[2][H_][52];
    __shared__ float2 wr2[H_][52];
    __shared__ float2 wp2[H_][16];
    __shared__ float2 w0a[H_], A1s[H_], A2s[H_];
    __shared__ float  tok[2][D_];
    __shared__ float  Gs[256], sks[H_][16], csums[16];
    __shared__ float  red[32];
    int t = threadIdx.x;

    for (int idx = t; idx < 2 * 784; idx += 256) {
        int bb = idx >= 784, i = idx - bb * 784;
        int R = i / 28, C = i % 28;
        P16[bb][(R >> 2) * 7 + (C >> 2)][(R & 3) * 4 + (C & 3)] = x[(size_t)(b0 + bb) * 784 + i];
    }
    if (t < 256) Gs[t] = g_G[t];
    for (int idx = t; idx < 256; idx += 256) sks[idx >> 4][idx & 15] = g_sk[idx];
    if (t < 16) csums[t] = g_csum[t];
    __syncthreads();

    if (t < 2 * P_) {
        int bb = t / P_, p = t - bb * P_, pos = p + 1;
        const float* Pp = P16[bb][p];
        float mu = g_pemean[pos];
        #pragma unroll
        for (int s = 0; s < 16; s++) mu += csums[s] * Pp[s];
        float e2 = g_pe2[pos];
        #pragma unroll
        for (int s = 0; s < 16; s++) {
            float acc = 0.f;
            #pragma unroll
            for (int u = 0; u < 16; u++) acc += Gs[s * 16 + u] * Pp[u];
            e2 += acc * Pp[s];
        }
        #pragma unroll
        for (int s = 0; s < 16; s++) e2 += 2.0f * g_gvec[pos * 16 + s] * Pp[s];
        float var = e2 - mu * mu;
        mu_s[bb][p] = mu;
        rs_s[bb][p] = rsqrtf(var + EPS_);
    }
    __syncthreads();

    for (int idx = t; idx < 2 * H_ * P_; idx += 256) {
        int bb = idx / (H_ * P_);
        int r = idx - bb * H_ * P_;
        int h = r / P_, p = r - h * P_, pos = p + 1;
        const float* Pp = P16[bb][p];
        float a = 0.f;
        #pragma unroll
        for (int s = 0; s < 16; s++) a += sks[h][s] * Pp[s];
        float sco = rs_s[bb][p] * (a + g_spk[h * S_ + pos] - mu_s[bb][p] * g_scw[h]) + g_scb[h];
        sc[bb][h][p + 1] = 32.0f * sco;
    }
    if (t < 32) sc[t >> 4][t & 15][0] = g_score0[t & 15];
    __syncthreads();

    if (t < 32) {
        int bb = t >> 4, h = t & 15;
        float m = sc[bb][h][0];
        for (int s = 1; s < S_; s++) m = fmaxf(m, sc[bb][h][s]);
        float sum = 0.f;
        for (int s = 0; s < S_; s++) { float e = expf(sc[bb][h][s] - m); sc[bb][h][s] = e; sum += e; }
        float inv = 1.f / sum;
        for (int s = 0; s < S_; s++) sc[bb][h][s] *= inv;
        float w0 = sc[bb][h][0];
        ((float*)&w0a[h])[bb] = w0;
        ((float*)&A2s[h])[bb] = 1.0f - w0;
    }
    __syncthreads();

    for (int idx = t; idx < 2 * H_ * P_; idx += 256) {
        int bb = idx / (H_ * P_);
        int r = idx - bb * H_ * P_;
        int h = r / P_, p = r - h * P_;
        ((float*)&wr2[h][p])[bb] = sc[bb][h][p + 1] * rs_s[bb][p];
    }
    __syncthreads();

    if (t < 32) {
        int bb = t >> 4, h = t & 15;
        float a = 0.f;
        for (int p = 0; p < P_; p++) a += ((float*)&wr2[h][p])[bb] * mu_s[bb][p];
        ((float*)&A1s[h])[bb] = a;
    }
    for (int idx = t; idx < 2 * H_ * 16; idx += 256) {
        int bb = idx >> 8, h = (idx >> 4) & 15, s = idx & 15;
        float a = 0.f;
        for (int p = 0; p < P_; p++) a += ((float*)&wr2[h][p])[bb] * P16[bb][p][s];
        ((float*)&wp2[h][s])[bb] = a;
    }
    __syncthreads();

    for (int o = t; o < D_; o += 256) {
        int h = o >> 6;
        float v0v = g_v0[o];
        float2 w0v = w0a[h];
        float a0 = w0v.x * v0v, a1 = w0v.y * v0v;
        #pragma unroll
        for (int s = 0; s < 16; s++) {
            float m = g_Mv[s * D_ + o];
            float2 wp = wp2[h][s];
            a0 += m * wp.x; a1 += m * wp.y;
        }
        #pragma unroll 7
        for (int p = 0; p < P_; p++) {
            float pv = g_pv[(p + 1) * D_ + o];
            float2 w = wr2[h][p];
            a0 += w.x * pv; a1 += w.y * pv;
        }
        float cvw = g_cvw[o], cvb = g_cvb[o], tc = g_tok0c[o];
        float2 a1v = A1s[h], a2v = A2s[h];
        float tk0 = tc + a0 - cvw * a1v.x + cvb * a2v.x;
        float tk1 = tc + a1 - cvw * a1v.y + cvb * a2v.y;
        tok[0][o] = tk0; tok[1][o] = tk1;
        g_tok0[(size_t)b0 * D_ + o]       = tk0;
        g_tok0[(size_t)(b0 + 1) * D_ + o] = tk1;
    }
    __syncthreads();

    for (int bb = 0; bb < 2; bb++) {
        float s = 0.f;
        for (int d = t; d < D_; d += 256) s += tok[bb][d];
        float mu = block_reduce_sum(s, red) * (1.0f / D_);
        float vs = 0.f;
        for (int d = t; d < D_; d += 256) { float dv = tok[bb][d] - mu; vs += dv * dv; }
        float var  = block_reduce_sum(vs, red) * (1.0f / D_);
        float rstd = rsqrtf(var + EPS_);
        size_t base = (size_t)(b0 + bb) * KP_;
        for (int d = t; d < D_; d += 256) {
            float z = (tok[bb][d] - mu) * rstd * ln2w[d] + ln2b[d];
            __nv_bfloat16 hi, lo; split_bf16(z, hi, lo);
            g_Zp[base + d]        = hi;
            g_Zp[base + 1024 + d] = hi;
            g_Zp[base + 2048 + d] = lo;
        }
    }
}

// ---------------- HMMA bf16 GEMM: 64x128 CTA tile, register prefetch -----------
template<int MODE>
__global__ __launch_bounds__(256) void gemm_tc(const float* __restrict__ bias) {
    __shared__ __nv_bfloat16 As[64][40];
    __shared__ __nv_bfloat16 Bs[128][40];
    int t = threadIdx.x;
    int wid = t >> 5, lane = t & 31;
    int warp_m = wid >> 2, warp_n = wid & 3;
    int m0 = blockIdx.y * 64, n0 = blockIdx.x * 128;

    const __nv_bfloat16* Ag = ((MODE == 0) ? g_Zp : g_Yp) + (size_t)m0 * KP_;
    const __nv_bfloat16* Bg = ((MODE == 0) ? g_Wmp : g_Whp) + (size_t)n0 * KP_;

    float acc[2][4][4];
    #pragma unroll
    for (int i = 0; i < 2; i++)
        #pragma unroll
        for (int j = 0; j < 4; j++)
            #pragma unroll
            for (int e = 0; e < 4; e++) acc[i][j][e] = 0.f;

    uint32_t As_base = smem_to_u32(&As[0][0]);
    uint32_t Bs_base = smem_to_u32(&Bs[0][0]);

    int ar = t >> 2, aseg = (t & 3) * 8;

    int a_row = warp_m * 32 + (lane & 15);
    int a_col8 = (lane >> 4) * 8;
    int b_quad = lane >> 3;
    int b_tile = b_quad >> 1;
    int b_seg8 = (b_quad & 1) * 8;
    int b_row = warp_n * 32 + (lane & 7);

    uint4 ra  = *(const uint4*)(Ag + (size_t)ar * KP_ + aseg);
    uint4 rb0 = *(const uint4*)(Bg + (size_t)ar * KP_ + aseg);
    uint4 rb1 = *(const uint4*)(Bg + (size_t)(ar + 64) * KP_ + aseg);

    for (int ch = 0; ch < NCH_; ch++) {
        *(uint4*)&As[ar][aseg]      = ra;
        *(uint4*)&Bs[ar][aseg]      = rb0;
        *(uint4*)&Bs[ar + 64][aseg] = rb1;
        __syncthreads();
        if (ch + 1 < NCH_) {
            int k0 = (ch + 1) * 32;
            ra  = *(const uint4*)(Ag + (size_t)ar * KP_ + k0 + aseg);
            rb0 = *(const uint4*)(Bg + (size_t)ar * KP_ + k0 + aseg);
            rb1 = *(const uint4*)(Bg + (size_t)(ar + 64) * KP_ + k0 + aseg);
        }
        #pragma unroll
        for (int ks = 0; ks < 2; ks++) {
            uint32_t a[2][4];
            #pragma unroll
            for (int i = 0; i < 2; i++) {
                uint32_t addr = As_base + (uint32_t)(((a_row + i * 16) * 40 + ks * 16 + a_col8) * 2);
                LDMATRIX_X4(a[i][0], a[i][1], a[i][2], a[i][3], addr);
            }
            uint32_t bfr[4][2];
            #pragma unroll
            for (int jp = 0; jp < 2; jp++) {
                uint32_t addr = Bs_base + (uint32_t)(((b_row + (jp * 2 + b_tile) * 8) * 40 + ks * 16 + b_seg8) * 2);
                uint32_t r0, r1, r2, r3;
                LDMATRIX_X4(r0, r1, r2, r3, addr);
                bfr[jp * 2][0] = r0; bfr[jp * 2][1] = r1;
                bfr[jp * 2 + 1][0] = r2; bfr[jp * 2 + 1][1] = r3;
            }
            #pragma unroll
            for (int i = 0; i < 2; i++)
                #pragma unroll
                for (int j = 0; j < 4; j++)
                    MMA_BF16(acc[i][j], a[i], bfr[j]);
        }
        __syncthreads();
    }

    int r4 = lane >> 2, c2 = (lane & 3) * 2;
    #pragma unroll
    for (int i = 0; i < 2; i++) {
        #pragma unroll
        for (int j = 0; j < 4; j++) {
            int n = n0 + warp_n * 32 + j * 8 + c2;
            #pragma unroll
            for (int half = 0; half < 2; half++) {
                int m = m0 + warp_m * 32 + i * 16 + r4 + half * 8;
                float v0 = acc[i][j][half * 2 + 0];
                float v1 = acc[i][j][half * 2 + 1];
                if (MODE == 0) {
                    v0 += bias[n]     + g_tok0[(size_t)m * D_ + n];
                    v1 += bias[n + 1] + g_tok0[(size_t)m * D_ + n + 1];
                    __nv_bfloat16 h0, l0, h1, l1;
                    split_bf16(v0, h0, l0); split_bf16(v1, h1, l1);
                    __nv_bfloat162 hp; hp.x = h0; hp.y = h1;
                    __nv_bfloat162 lp; lp.x = l0; lp.y = l1;
                    *(__nv_bfloat162*)&g_Yp[(size_t)m * KP_ + n]        = hp;
                    *(__nv_bfloat162*)&g_Yp[(size_t)m * KP_ + 1024 + n] = hp;
                    *(__nv_bfloat162*)&g_Yp[(size_t)m * KP_ + 2048 + n] = lp;
                } else {
                    if (n < OUT_)     g_logits[(size_t)m * OUT_ + n]     = v0 + bias[n];
                    if (n + 1 < OUT_) g_logits[(size_t)m * OUT_ + n + 1] = v1 + bias[n + 1];
                }
            }
        }
    }
}

// ---------------- K5: row softmax (exp cached in registers) ---------------------
__global__ __launch_bounds__(256) void k5_softmax(float* __restrict__ out) {
    int b = blockIdx.x;
    __shared__ float red[32];
    int t = threadIdx.x;
    const float* lg = g_logits + (size_t)b * OUT_;

    float m = -1e30f;
    float lv[4];
    int cnt = 0;
    for (int o = t; o < OUT_; o += 256) { lv[cnt] = lg[o]; m = fmaxf(m, lv[cnt]); cnt++; }
    m = block_reduce_max(m, red);

    float s = 0.f;
    float ev[4];
    for (int i = 0; i < cnt; i++) { ev[i] = expf(lv[i] - m); s += ev[i]; }
    float sum = block_reduce_sum(s, red);
    float inv = 1.f / sum;

    float* ob = out + (size_t)b * OUT_;
    int i = 0;
    for (int o = t; o < OUT_; o += 256, i++) ob[o] = ev[i] * inv;
}

// ---------------- launch ----------------------------------------------------------
extern "C" void kernel_launch(void* const* d_in, const int* in_sizes, int n_in,
                              void* d_out, int out_size) {
    const float* x    = (const float*)d_in[0];
    const float* cls  = (const float*)d_in[1];
    const float* Wp   = (const float*)d_in[2];
    const float* ln1w = (const float*)d_in[3];
    const float* ln1b = (const float*)d_in[4];
    const float* Wq   = (const float*)d_in[5];
    const float* bq   = (const float*)d_in[6];
    const float* Wk   = (const float*)d_in[7];
    const float* bk   = (const float*)d_in[8];
    const float* Wv   = (const float*)d_in[9];
    const float* bv   = (const float*)d_in[10];
    const float* ln2w = (const float*)d_in[11];
    const float* ln2b = (const float*)d_in[12];
    const float* Wm   = (const float*)d_in[13];
    const float* bm   = (const float*)d_in[14];
    const float* Wh   = (const float*)d_in[15];
    const float* bh   = (const float*)d_in[16];
    float* out = (float*)d_out;

    cudaFuncSetAttribute(k0_mega, cudaFuncAttributeMaxDynamicSharedMemorySize, MEGA_SMEM);

    k0_mega<<<579, 1024, MEGA_SMEM>>>(cls, ln1w, ln1b, Wp, Wq, bq, Wk, bk, Wv, bv, Wm, Wh);

    k_main<<<B_ / 2, 256>>>(x, ln2w, ln2b);

    dim3 g(8, 16);
    gemm_tc<0><<<g, 256>>>(bm);
    gemm_tc<1><<<g, 256>>>(bh);

    k5_softmax<<<B_, 256>>>(out);
}

// round 10
// speedup vs baseline: 16.3422x; 1.1910x over previous
#include <cuda_runtime.h>
#include <cuda_bf16.h>
#include <cstdint>
#include <math.h>

#define B_    1024
#define D_    1024
#define H_    16
#define S_    50
#define P_    49
#define OUT_  1000
#define EPS_  1e-5f
#define KP_   3072          // bf16x3 expanded K
#define NCH_  96            // KP_/32
#define STG_  3             // cp.async pipeline depth

// ---------------- scratch / tables (device globals) -------------------------
__device__ float g_pemean[S_], g_pe2[S_];
__device__ float g_gvec[S_*16];
__device__ float g_csum[16];
__device__ float g_G[16*16];
__device__ float g_tok0c[D_];
__device__ float g_v0[D_];
__device__ float g_score0[H_];
__device__ float g_sk[H_*16], g_spk[H_*S_], g_scw[H_], g_scb[H_];
__device__ float g_Mv[16*D_];
__device__ float g_pv[S_*D_];
__device__ float g_cvw[D_], g_cvb[D_];
__device__ float g_tok0[(size_t)B_*D_];
__device__ float g_logits[(size_t)B_*OUT_];
__device__ __nv_bfloat16 g_Zp[(size_t)B_*KP_];          // Z'  [hi|hi|lo]
__device__ __nv_bfloat16 g_Yp[(size_t)B_*KP_];          // Y'  [hi|hi|lo]
__device__ __nv_bfloat16 g_Wmp[(size_t)1024*KP_];       // Wm' [hi|lo|hi]
__device__ __nv_bfloat16 g_Whp[(size_t)1024*KP_];       // Wh' [hi|lo|hi]

// ---------------- PTX helpers ------------------------------------------------
__device__ __forceinline__ uint32_t smem_to_u32(const void* p) {
    uint32_t a;
    asm("{ .reg .u64 tmp; cvta.to.shared.u64 tmp, %1; cvt.u32.u64 %0, tmp; }" : "=r"(a) : "l"(p));
    return a;
}
#define LDMATRIX_X4(r0, r1, r2, r3, addr) \
    asm volatile("ldmatrix.sync.aligned.m8n8.x4.shared.b16 {%0,%1,%2,%3}, [%4];" \
        : "=r"(r0), "=r"(r1), "=r"(r2), "=r"(r3) : "r"(addr))
#define MMA_BF16(d, a, b) \
    asm volatile("mma.sync.aligned.m16n8k16.row.col.f32.bf16.bf16.f32 " \
        "{%0,%1,%2,%3}, {%4,%5,%6,%7}, {%8,%9}, {%0,%1,%2,%3};" \
        : "+f"((d)[0]), "+f"((d)[1]), "+f"((d)[2]), "+f"((d)[3]) \
        : "r"((a)[0]), "r"((a)[1]), "r"((a)[2]), "r"((a)[3]), "r"((b)[0]), "r"((b)[1]))
#define CP_ASYNC16(dst, src) \
    asm volatile("cp.async.cg.shared.global [%0], [%1], 16;" :: "r"(dst), "l"(src))
#define CP_COMMIT() asm volatile("cp.async.commit_group;" ::: "memory")
#define CP_WAIT1()  asm volatile("cp.async.wait_group 1;" ::: "memory")

// ---------------- math helpers ------------------------------------------------
__device__ __forceinline__ float pos_emb(int pos, int d) {
    float fd    = (float)(d & ~1);
    float denom = powf(10000.0f, fd * (1.0f / 1024.0f));
    float ang   = (float)pos / denom;
    return (d & 1) ? cosf(ang) : sinf(ang);
}
__device__ __forceinline__ float block_reduce_sum(float v, float* red) {
    int t = threadIdx.x;
    #pragma unroll
    for (int o = 16; o > 0; o >>= 1) v += __shfl_down_sync(0xffffffffu, v, o);
    if ((t & 31) == 0) red[t >> 5] = v;
    __syncthreads();
    if (t == 0) {
        float s = 0.f; int nw = blockDim.x >> 5;
        for (int i = 0; i < nw; i++) s += red[i];
        red[0] = s;
    }
    __syncthreads();
    float r = red[0];
    __syncthreads();
    return r;
}
__device__ __forceinline__ float block_reduce_max(float v, float* red) {
    int t = threadIdx.x;
    #pragma unroll
    for (int o = 16; o > 0; o >>= 1) v = fmaxf(v, __shfl_down_sync(0xffffffffu, v, o));
    if ((t & 31) == 0) red[t >> 5] = v;
    __syncthreads();
    if (t == 0) {
        float m = red[0]; int nw = blockDim.x >> 5;
        for (int i = 1; i < nw; i++) m = fmaxf(m, red[i]);
        red[0] = m;
    }
    __syncthreads();
    float r = red[0];
    __syncthreads();
    return r;
}
__device__ __forceinline__ void split_bf16(float x, __nv_bfloat16& hi, __nv_bfloat16& lo) {
    hi = __float2bfloat16(x);
    lo = __float2bfloat16(x - __bfloat162float(hi));
}

// ---------------- K0 MEGA: all precompute in one launch -------------------------
#define MEGA_SMEM (18500 * 4)
__global__ __launch_bounds__(1024) void k0_mega(
    const float* __restrict__ cls, const float* __restrict__ ln1w, const float* __restrict__ ln1b,
    const float* __restrict__ Wp,
    const float* __restrict__ Wq, const float* __restrict__ bq,
    const float* __restrict__ Wk, const float* __restrict__ bk,
    const float* __restrict__ Wv, const float* __restrict__ bv,
    const float* __restrict__ Wm, const float* __restrict__ Wh)
{
    extern __shared__ float sm[];
    int bid = blockIdx.x;
    int t = threadIdx.x;

    if (bid < 512) {               // ---- conv role: 4 floats per thread --------
        int idx4 = bid * 1024 + t;
        int which = idx4 >= (1 << 18);
        int l4 = idx4 & ((1 << 18) - 1);
        int r = l4 >> 8;
        int k4 = (l4 & 255) * 4;
        const float* W = which ? Wh : Wm;
        int rows = which ? OUT_ : 1024;
        float4 v = make_float4(0.f, 0.f, 0.f, 0.f);
        if (r < rows) v = *(const float4*)&W[(size_t)r * 1024 + k4];
        __nv_bfloat16 h0, l0, h1, l1, h2, l2, h3, l3;
        split_bf16(v.x, h0, l0); split_bf16(v.y, h1, l1);
        split_bf16(v.z, h2, l2); split_bf16(v.w, h3, l3);
        __nv_bfloat162 hp0, hp1, lp0, lp1;
        hp0.x = h0; hp0.y = h1; hp1.x = h2; hp1.y = h3;
        lp0.x = l0; lp0.y = l1; lp1.x = l2; lp1.y = l3;
        __nv_bfloat16* dst = which ? g_Whp : g_Wmp;
        size_t base = (size_t)r * KP_ + k4;
        // B-operand layout is [hi | lo | hi]  (pairs with A's [hi | hi | lo])
        *(__nv_bfloat162*)&dst[base]            = hp0;
        *(__nv_bfloat162*)&dst[base + 2]        = hp1;
        *(__nv_bfloat162*)&dst[base + 1024]     = lp0;
        *(__nv_bfloat162*)&dst[base + 1026]     = lp1;
        *(__nv_bfloat162*)&dst[base + 2048]     = hp0;
        *(__nv_bfloat162*)&dst[base + 2050]     = hp1;
        return;
    }

    if (bid < 562) {               // ---- pe-pos role -----------------------------
        float* pes     = sm;
        float* partial = sm + 1024;
        float* red     = sm + 1024 + 1088;
        int pos = bid - 512;
        float v = pos_emb(pos, t);
        pes[t] = v;
        __syncthreads();
        float mean = block_reduce_sum(v, red) * (1.0f / D_);
        float m2   = block_reduce_sum(v * v, red) * (1.0f / D_);
        if (t == 0) { g_pemean[pos] = mean; g_pe2[pos] = m2; }

        int s = t & 15, grp = t >> 4;
        float acc = 0.f;
        #pragma unroll
        for (int i = 0; i < 16; i++) {
            int d = grp * 16 + i;
            acc += Wp[d * 16 + s] * pes[d];
        }
        partial[grp * 17 + s] = acc;
        __syncthreads();
        if (t < 16) {
            float a = 0.f;
            for (int g = 0; g < 64; g++) a += partial[g * 17 + t];
            g_gvec[pos * 16 + t] = a * (1.0f / D_);
        }
        return;
    }

    if (bid == 562) {              // ---- Gram role (full 16384-float Wp) --------
        float* wps     = sm;               // 16384
        float* qpart   = sm + 16384;       // 1024
        float* partial = sm + 17408;       // 1088
        for (int idx = t; idx < 16384; idx += 1024) wps[idx] = Wp[idx];
        __syncthreads();
        {
            int p = t & 255, q = t >> 8;
            int si = p >> 4, tj = p & 15;
            float acc = 0.f;
            #pragma unroll 8
            for (int i = 0; i < 256; i++) {
                int d = q * 256 + i;
                acc += wps[d * 16 + si] * wps[d * 16 + tj];
            }
            qpart[q * 256 + p] = acc;
        }
        {
            int s = t & 15, grp = t >> 4;
            float ac = 0.f;
            #pragma unroll
            for (int i = 0; i < 16; i++) ac += wps[(grp * 16 + i) * 16 + s];
            partial[grp * 17 + s] = ac;
        }
        __syncthreads();
        if (t < 256)
            g_G[t] = (qpart[t] + qpart[256 + t] + qpart[512 + t] + qpart[768 + t]) * (1.0f / D_);
        if (t < 16) {
            float a = 0.f;
            for (int g = 0; g < 64; g++) a += partial[g * 17 + t];
            g_csum[t] = a * (1.0f / D_);
        }
        return;
    }

    // ---- head role -------------------------------------------------------------
    int h = bid - 563;
    float* Wqs  = sm;
    float* Wks  = sm + 4160;
    float* Wvs  = sm + 8320;
    float* wpw  = sm + 12480;
    float* pew  = sm + 13568;
    float* toks = sm + 16818;
    float* n0s  = sm + 17842;
    float* qs   = sm + 17906;
    float* ks   = sm + 17970;
    float* qkr  = sm + 18034;
    float* red  = sm + 18098;

    for (int idx = t; idx < 4096; idx += 1024) {
        int e = idx >> 6, d = idx & 63;
        Wqs[e * 65 + d] = Wq[(size_t)h * 4096 + idx];
        Wks[e * 65 + d] = Wk[(size_t)h * 4096 + idx];
        Wvs[e * 65 + d] = Wv[(size_t)h * 4096 + idx];
    }
    float tv = cls[t] + (float)(t & 1);
    toks[t] = tv;
    {
        int dp = t >> 4, s = t & 15;
        wpw[dp * 17 + s] = Wp[(h * 64 + dp) * 16 + s] * ln1w[h * 64 + dp];
    }
    __syncthreads();
    float mu = block_reduce_sum(tv, red) * (1.0f / D_);
    float dv = tv - mu;
    float var  = block_reduce_sum(dv * dv, red) * (1.0f / D_);
    float rstd = rsqrtf(var + EPS_);
    if (t < 64) {
        int d = h * 64 + t;
        n0s[t] = (toks[d] - mu) * rstd * ln1w[d] + ln1b[d];
    }
    if (h == 0) g_tok0c[t] = tv;
    for (int idx = t; idx < 3200; idx += 1024) {
        int pos = idx >> 6, dp = idx & 63;
        int d = h * 64 + dp;
        pew[pos * 65 + dp] = pos_emb(pos, d) * ln1w[d];
    }
    __syncthreads();

    if (t < 64) {               // q
        float a = 0.f;
        #pragma unroll 16
        for (int d = 0; d < 64; d++) a += n0s[d] * Wqs[t * 65 + d];
        qs[t] = a + bq[h * 64 + t];
    } else if (t < 128) {       // k
        int e = t - 64;
        float a = 0.f;
        #pragma unroll 16
        for (int d = 0; d < 64; d++) a += n0s[d] * Wks[e * 65 + d];
        ks[e] = a + bk[h * 64 + e];
    } else if (t < 192) {       // v
        int e = t - 128;
        float a = 0.f;
        #pragma unroll 16
        for (int d = 0; d < 64; d++) a += n0s[d] * Wvs[e * 65 + d];
        g_v0[h * 64 + e] = a + bv[h * 64 + e];
    }
    __syncthreads();

    if (t < 64) {               // score0
        float p = qs[t] * ks[t];
        #pragma unroll
        for (int o = 16; o > 0; o >>= 1) p += __shfl_down_sync(0xffffffffu, p, o);
        if (t == 0)  red[0] = p;
        if (t == 32) red[1] = p;
    }
    if (t >= 64 && t < 128) {   // qk
        int dp = t - 64;
        float a = 0.f;
        #pragma unroll 16
        for (int e = 0; e < 64; e++) a += qs[e] * Wks[e * 65 + dp];
        qkr[dp] = a;
    }
    __syncthreads();
    if (t == 0) g_score0[h] = 32.0f * (red[0] + red[1]);

    {
        int e = t >> 4, s = t & 15;
        float a = 0.f;
        #pragma unroll 16
        for (int d = 0; d < 64; d++) a += Wvs[e * 65 + d] * wpw[d * 17 + s];
        g_Mv[s * D_ + h * 64 + e] = a;
    }
    for (int idx = t; idx < 3200; idx += 1024) {
        int e = idx / S_, pos = idx % S_;
        float a = 0.f;
        #pragma unroll 16
        for (int d = 0; d < 64; d++) a += Wvs[e * 65 + d] * pew[pos * 65 + d];
        g_pv[pos * D_ + h * 64 + e] = a;
    }
    if (t < 64) {
        float aw = 0.f, ab = 0.f;
        #pragma unroll 16
        for (int d = 0; d < 64; d++) {
            float wvd = Wvs[t * 65 + d];
            aw += wvd * ln1w[h * 64 + d];
            ab += wvd * ln1b[h * 64 + d];
        }
        g_cvw[h * 64 + t] = aw;
        g_cvb[h * 64 + t] = ab + bv[h * 64 + t];
    }
    if (t >= 64 && t < 80) {
        int s = t - 64;
        float a = 0.f;
        for (int d = 0; d < 64; d++) a += qkr[d] * wpw[d * 17 + s];
        g_sk[h * 16 + s] = a;
    }
    if (t >= 128 && t < 128 + S_) {
        int pos = t - 128;
        float a = 0.f;
        for (int d = 0; d < 64; d++) a += qkr[d] * pew[pos * 65 + d];
        g_spk[h * S_ + pos] = a;
    }
    if (t == 200) {
        float aw = 0.f, ab = 0.f;
        for (int d = 0; d < 64; d++) {
            aw += qkr[d] * ln1w[h * 64 + d];
            ab += qkr[d] * ln1b[h * 64 + d];
        }
        float qb = 0.f;
        for (int e = 0; e < 64; e++) qb += qs[e] * bk[h * 64 + e];
        g_scw[h] = aw;
        g_scb[h] = ab + qb;
    }
}

// ---------------- K_MAIN: 2 batches per block ----------------------------------
__global__ __launch_bounds__(256) void k_main(
    const float* __restrict__ x,
    const float* __restrict__ ln2w, const float* __restrict__ ln2b)
{
    int b0 = blockIdx.x * 2;
    __shared__ float  P16[2][P_][16];
    __shared__ float  mu_s[2][P_], rs_s[2][P_];
    __shared__ float  sc[2][H_][52];
    __shared__ float2 wr2[H_][52];
    __shared__ float2 wp2[H_][16];
    __shared__ float2 w0a[H_], A1s[H_], A2s[H_];
    __shared__ float  tok[2][D_];
    __shared__ float  Gs[256], sks[H_][16], csums[16];
    __shared__ float  red[32];
    int t = threadIdx.x;

    for (int idx = t; idx < 2 * 784; idx += 256) {
        int bb = idx >= 784, i = idx - bb * 784;
        int R = i / 28, C = i % 28;
        P16[bb][(R >> 2) * 7 + (C >> 2)][(R & 3) * 4 + (C & 3)] = x[(size_t)(b0 + bb) * 784 + i];
    }
    if (t < 256) Gs[t] = g_G[t];
    for (int idx = t; idx < 256; idx += 256) sks[idx >> 4][idx & 15] = g_sk[idx];
    if (t < 16) csums[t] = g_csum[t];
    __syncthreads();

    if (t < 2 * P_) {
        int bb = t / P_, p = t - bb * P_, pos = p + 1;
        const float* Pp = P16[bb][p];
        float mu = g_pemean[pos];
        #pragma unroll
        for (int s = 0; s < 16; s++) mu += csums[s] * Pp[s];
        float e2 = g_pe2[pos];
        #pragma unroll
        for (int s = 0; s < 16; s++) {
            float acc = 0.f;
            #pragma unroll
            for (int u = 0; u < 16; u++) acc += Gs[s * 16 + u] * Pp[u];
            e2 += acc * Pp[s];
        }
        #pragma unroll
        for (int s = 0; s < 16; s++) e2 += 2.0f * g_gvec[pos * 16 + s] * Pp[s];
        float var = e2 - mu * mu;
        mu_s[bb][p] = mu;
        rs_s[bb][p] = rsqrtf(var + EPS_);
    }
    __syncthreads();

    for (int idx = t; idx < 2 * H_ * P_; idx += 256) {
        int bb = idx / (H_ * P_);
        int r = idx - bb * H_ * P_;
        int h = r / P_, p = r - h * P_, pos = p + 1;
        const float* Pp = P16[bb][p];
        float a = 0.f;
        #pragma unroll
        for (int s = 0; s < 16; s++) a += sks[h][s] * Pp[s];
        float sco = rs_s[bb][p] * (a + g_spk[h * S_ + pos] - mu_s[bb][p] * g_scw[h]) + g_scb[h];
        sc[bb][h][p + 1] = 32.0f * sco;
    }
    if (t < 32) sc[t >> 4][t & 15][0] = g_score0[t & 15];
    __syncthreads();

    if (t < 32) {
        int bb = t >> 4, h = t & 15;
        float m = sc[bb][h][0];
        for (int s = 1; s < S_; s++) m = fmaxf(m, sc[bb][h][s]);
        float sum = 0.f;
        for (int s = 0; s < S_; s++) { float e = expf(sc[bb][h][s] - m); sc[bb][h][s] = e; sum += e; }
        float inv = 1.f / sum;
        for (int s = 0; s < S_; s++) sc[bb][h][s] *= inv;
        float w0 = sc[bb][h][0];
        ((float*)&w0a[h])[bb] = w0;
        ((float*)&A2s[h])[bb] = 1.0f - w0;
    }
    __syncthreads();

    for (int idx = t; idx < 2 * H_ * P_; idx += 256) {
        int bb = idx / (H_ * P_);
        int r = idx - bb * H_ * P_;
        int h = r / P_, p = r - h * P_;
        ((float*)&wr2[h][p])[bb] = sc[bb][h][p + 1] * rs_s[bb][p];
    }
    __syncthreads();

    if (t < 32) {
        int bb = t >> 4, h = t & 15;
        float a = 0.f;
        for (int p = 0; p < P_; p++) a += ((float*)&wr2[h][p])[bb] * mu_s[bb][p];
        ((float*)&A1s[h])[bb] = a;
    }
    for (int idx = t; idx < 2 * H_ * 16; idx += 256) {
        int bb = idx >> 8, h = (idx >> 4) & 15, s = idx & 15;
        float a = 0.f;
        for (int p = 0; p < P_; p++) a += ((float*)&wr2[h][p])[bb] * P16[bb][p][s];
        ((float*)&wp2[h][s])[bb] = a;
    }
    __syncthreads();

    for (int o = t; o < D_; o += 256) {
        int h = o >> 6;
        float v0v = g_v0[o];
        float2 w0v = w0a[h];
        float a0 = w0v.x * v0v, a1 = w0v.y * v0v;
        #pragma unroll
        for (int s = 0; s < 16; s++) {
            float m = g_Mv[s * D_ + o];
            float2 wp = wp2[h][s];
            a0 += m * wp.x; a1 += m * wp.y;
        }
        #pragma unroll 7
        for (int p = 0; p < P_; p++) {
            float pv = g_pv[(p + 1) * D_ + o];
            float2 w = wr2[h][p];
            a0 += w.x * pv; a1 += w.y * pv;
        }
        float cvw = g_cvw[o], cvb = g_cvb[o], tc = g_tok0c[o];
        float2 a1v = A1s[h], a2v = A2s[h];
        float tk0 = tc + a0 - cvw * a1v.x + cvb * a2v.x;
        float tk1 = tc + a1 - cvw * a1v.y + cvb * a2v.y;
        tok[0][o] = tk0; tok[1][o] = tk1;
        g_tok0[(size_t)b0 * D_ + o]       = tk0;
        g_tok0[(size_t)(b0 + 1) * D_ + o] = tk1;
    }
    __syncthreads();

    for (int bb = 0; bb < 2; bb++) {
        float s = 0.f;
        for (int d = t; d < D_; d += 256) s += tok[bb][d];
        float mu = block_reduce_sum(s, red) * (1.0f / D_);
        float vs = 0.f;
        for (int d = t; d < D_; d += 256) { float dv = tok[bb][d] - mu; vs += dv * dv; }
        float var  = block_reduce_sum(vs, red) * (1.0f / D_);
        float rstd = rsqrtf(var + EPS_);
        size_t base = (size_t)(b0 + bb) * KP_;
        for (int d = t; d < D_; d += 256) {
            float z = (tok[bb][d] - mu) * rstd * ln2w[d] + ln2b[d];
            __nv_bfloat16 hi, lo; split_bf16(z, hi, lo);
            g_Zp[base + d]        = hi;
            g_Zp[base + 1024 + d] = hi;
            g_Zp[base + 2048 + d] = lo;
        }
    }
}

// ---------------- HMMA bf16 GEMM: 64x128 tile, 3-stage cp.async pipeline --------
template<int MODE>
__global__ __launch_bounds__(256) void gemm_tc(const float* __restrict__ bias) {
    __shared__ __nv_bfloat16 As[STG_][64][40];
    __shared__ __nv_bfloat16 Bs[STG_][128][40];
    int t = threadIdx.x;
    int wid = t >> 5, lane = t & 31;
    int warp_m = wid >> 2, warp_n = wid & 3;
    int m0 = blockIdx.y * 64, n0 = blockIdx.x * 128;

    const __nv_bfloat16* Ag = ((MODE == 0) ? g_Zp : g_Yp) + (size_t)m0 * KP_;
    const __nv_bfloat16* Bg = ((MODE == 0) ? g_Wmp : g_Whp) + (size_t)n0 * KP_;

    float acc[2][4][4];
    #pragma unroll
    for (int i = 0; i < 2; i++)
        #pragma unroll
        for (int j = 0; j < 4; j++)
            #pragma unroll
            for (int e = 0; e < 4; e++) acc[i][j][e] = 0.f;

    uint32_t As_base = smem_to_u32(&As[0][0][0]);
    uint32_t Bs_base = smem_to_u32(&Bs[0][0][0]);
    const uint32_t A_STAGE = 64 * 40 * 2;    // 5120 B
    const uint32_t B_STAGE = 128 * 40 * 2;   // 10240 B

    int ar = t >> 2, aseg = (t & 3) * 8;     // 64 rows x 4 16B-segs

    int a_row = warp_m * 32 + (lane & 15);
    int a_col8 = (lane >> 4) * 8;
    int b_quad = lane >> 3;
    int b_tile = b_quad >> 1;
    int b_seg8 = (b_quad & 1) * 8;
    int b_row = warp_n * 32 + (lane & 7);

    uint32_t a_dst = As_base + (uint32_t)((ar * 40 + aseg) * 2);
    uint32_t b_dst0 = Bs_base + (uint32_t)((ar * 40 + aseg) * 2);
    uint32_t b_dst1 = Bs_base + (uint32_t)(((ar + 64) * 40 + aseg) * 2);
    const __nv_bfloat16* a_src = Ag + (size_t)ar * KP_ + aseg;
    const __nv_bfloat16* b_src0 = Bg + (size_t)ar * KP_ + aseg;
    const __nv_bfloat16* b_src1 = Bg + (size_t)(ar + 64) * KP_ + aseg;

    // prefetch stages 0..STG_-2
    #pragma unroll
    for (int s = 0; s < STG_ - 1; s++) {
        int k0 = s * 32;
        CP_ASYNC16(a_dst + s * A_STAGE, a_src + k0);
        CP_ASYNC16(b_dst0 + s * B_STAGE, b_src0 + k0);
        CP_ASYNC16(b_dst1 + s * B_STAGE, b_src1 + k0);
        CP_COMMIT();
    }

    for (int ch = 0; ch < NCH_; ch++) {
        CP_WAIT1();
        __syncthreads();

        int nxt = ch + STG_ - 1;
        if (nxt < NCH_) {
            int buf = nxt % STG_;
            int k0 = nxt * 32;
            CP_ASYNC16(a_dst + buf * A_STAGE, a_src + k0);
            CP_ASYNC16(b_dst0 + buf * B_STAGE, b_src0 + k0);
            CP_ASYNC16(b_dst1 + buf * B_STAGE, b_src1 + k0);
        }
        CP_COMMIT();   // commit every iteration (possibly empty) to keep group count in lockstep

        int cur = ch % STG_;
        uint32_t Ab = As_base + cur * A_STAGE;
        uint32_t Bb = Bs_base + cur * B_STAGE;
        #pragma unroll
        for (int ks = 0; ks < 2; ks++) {
            uint32_t a[2][4];
            #pragma unroll
            for (int i = 0; i < 2; i++) {
                uint32_t addr = Ab + (uint32_t)(((a_row + i * 16) * 40 + ks * 16 + a_col8) * 2);
                LDMATRIX_X4(a[i][0], a[i][1], a[i][2], a[i][3], addr);
            }
            uint32_t bfr[4][2];
            #pragma unroll
            for (int jp = 0; jp < 2; jp++) {
                uint32_t addr = Bb + (uint32_t)(((b_row + (jp * 2 + b_tile) * 8) * 40 + ks * 16 + b_seg8) * 2);
                uint32_t r0, r1, r2, r3;
                LDMATRIX_X4(r0, r1, r2, r3, addr);
                bfr[jp * 2][0] = r0; bfr[jp * 2][1] = r1;
                bfr[jp * 2 + 1][0] = r2; bfr[jp * 2 + 1][1] = r3;
            }
            #pragma unroll
            for (int i = 0; i < 2; i++)
                #pragma unroll
                for (int j = 0; j < 4; j++)
                    MMA_BF16(acc[i][j], a[i], bfr[j]);
        }
    }

    int r4 = lane >> 2, c2 = (lane & 3) * 2;
    #pragma unroll
    for (int i = 0; i < 2; i++) {
        #pragma unroll
        for (int j = 0; j < 4; j++) {
            int n = n0 + warp_n * 32 + j * 8 + c2;
            #pragma unroll
            for (int half = 0; half < 2; half++) {
                int m = m0 + warp_m * 32 + i * 16 + r4 + half * 8;
                float v0 = acc[i][j][half * 2 + 0];
                float v1 = acc[i][j][half * 2 + 1];
                if (MODE == 0) {
                    v0 += bias[n]     + g_tok0[(size_t)m * D_ + n];
                    v1 += bias[n + 1] + g_tok0[(size_t)m * D_ + n + 1];
                    __nv_bfloat16 h0, l0, h1, l1;
                    split_bf16(v0, h0, l0); split_bf16(v1, h1, l1);
                    __nv_bfloat162 hp; hp.x = h0; hp.y = h1;
                    __nv_bfloat162 lp; lp.x = l0; lp.y = l1;
                    *(__nv_bfloat162*)&g_Yp[(size_t)m * KP_ + n]        = hp;
                    *(__nv_bfloat162*)&g_Yp[(size_t)m * KP_ + 1024 + n] = hp;
                    *(__nv_bfloat162*)&g_Yp[(size_t)m * KP_ + 2048 + n] = lp;
                } else {
                    if (n < OUT_)     g_logits[(size_t)m * OUT_ + n]     = v0 + bias[n];
                    if (n + 1 < OUT_) g_logits[(size_t)m * OUT_ + n + 1] = v1 + bias[n + 1];
                }
            }
        }
    }
}

// ---------------- K5: row softmax (exp cached in registers) ---------------------
__global__ __launch_bounds__(256) void k5_softmax(float* __restrict__ out) {
    int b = blockIdx.x;
    __shared__ float red[32];
    int t = threadIdx.x;
    const float* lg = g_logits + (size_t)b * OUT_;

    float m = -1e30f;
    float lv[4];
    int cnt = 0;
    for (int o = t; o < OUT_; o += 256) { lv[cnt] = lg[o]; m = fmaxf(m, lv[cnt]); cnt++; }
    m = block_reduce_max(m, red);

    float s = 0.f;
    float ev[4];
    for (int i = 0; i < cnt; i++) { ev[i] = expf(lv[i] - m); s += ev[i]; }
    float sum = block_reduce_sum(s, red);
    float inv = 1.f / sum;

    float* ob = out + (size_t)b * OUT_;
    int i = 0;
    for (int o = t; o < OUT_; o += 256, i++) ob[o] = ev[i] * inv;
}

// ---------------- launch ----------------------------------------------------------
extern "C" void kernel_launch(void* const* d_in, const int* in_sizes, int n_in,
                              void* d_out, int out_size) {
    const float* x    = (const float*)d_in[0];
    const float* cls  = (const float*)d_in[1];
    const float* Wp   = (const float*)d_in[2];
    const float* ln1w = (const float*)d_in[3];
    const float* ln1b = (const float*)d_in[4];
    const float* Wq   = (const float*)d_in[5];
    const float* bq   = (const float*)d_in[6];
    const float* Wk   = (const float*)d_in[7];
    const float* bk   = (const float*)d_in[8];
    const float* Wv   = (const float*)d_in[9];
    const float* bv   = (const float*)d_in[10];
    const float* ln2w = (const float*)d_in[11];
    const float* ln2b = (const float*)d_in[12];
    const float* Wm   = (const float*)d_in[13];
    const float* bm   = (const float*)d_in[14];
    const float* Wh   = (const float*)d_in[15];
    const float* bh   = (const float*)d_in[16];
    float* out = (float*)d_out;

    cudaFuncSetAttribute(k0_mega, cudaFuncAttributeMaxDynamicSharedMemorySize, MEGA_SMEM);

    k0_mega<<<579, 1024, MEGA_SMEM>>>(cls, ln1w, ln1b, Wp, Wq, bq, Wk, bk, Wv, bv, Wm, Wh);

    k_main<<<B_ / 2, 256>>>(x, ln2w, ln2b);

    dim3 g(8, 16);
    gemm_tc<0><<<g, 256>>>(bm);
    gemm_tc<1><<<g, 256>>>(bh);

    k5_softmax<<<B_, 256>>>(out);
}